// round 1
// baseline (speedup 1.0000x reference)
#include <cuda_runtime.h>
#include <math.h>

#define B_  2
#define S_  2048
#define H_  2048
#define NH_ 16
#define HD_ 128
#define M_  (B_*S_)   // 4096

// ---------------- scratch (device globals; no allocation allowed) ----------
__device__ float g_q[B_*NH_*S_*HD_];      // [B,NH,S,HD]
__device__ float g_k[B_*NH_*S_*HD_];
__device__ float g_v[B_*NH_*S_*HD_];
__device__ float g_attn[M_*H_];           // [B*S, NH*HD]
__device__ float g_cos[S_*64];
__device__ float g_sin[S_*64];

// ---------------- RoPE table ----------------------------------------------
__global__ void rope_table_kernel()
{
    int idx = blockIdx.x * blockDim.x + threadIdx.x;
    if (idx >= S_ * 64) return;
    int s = idx >> 6, p = idx & 63;
    double invf = exp(-log(10000.0) * (double)p / 64.0);
    double ang  = (double)s * invf;
    g_cos[idx] = (float)cos(ang);
    g_sin[idx] = (float)sin(ang);
}

// ---------------- shared 128x128x2048 fp32 GEMM mainloop -------------------
// 256 threads, BM=BN=128, BK=16, 8x8 per-thread tile.
// Thread (ty,tx): rows {ty*4+i, 64+ty*4+i}, cols {tx*4+j, 64+tx*4+j}.
__device__ __forceinline__ void gemm_tile(const float* __restrict__ A,
                                          const float* __restrict__ Bm,
                                          float* As, float* Bs,
                                          int m0, int n0, float acc[8][8])
{
    const int tid = threadIdx.x;
    const int ty = tid >> 4, tx = tid & 15;
    const int ra = tid >> 2, ca = (tid & 3) << 2;   // A loader: 64 rows x 4 col-groups
    const int rb = tid >> 5, cb = (tid & 31) << 2;  // B loader: 8 rows x 32 col-groups

#pragma unroll
    for (int i = 0; i < 8; i++)
#pragma unroll
        for (int j = 0; j < 8; j++) acc[i][j] = 0.f;

    for (int kt = 0; kt < H_; kt += 16) {
        float4 a0 = *(const float4*)&A[(m0 + ra)      * H_ + kt + ca];
        float4 a1 = *(const float4*)&A[(m0 + ra + 64) * H_ + kt + ca];
        float4 b0 = *(const float4*)&Bm[(kt + rb)     * H_ + n0 + cb];
        float4 b1 = *(const float4*)&Bm[(kt + rb + 8) * H_ + n0 + cb];
        __syncthreads();
        // A stored k-major (transposed) for broadcast-friendly compute reads
        As[(ca+0)*128 + ra]      = a0.x;
        As[(ca+1)*128 + ra]      = a0.y;
        As[(ca+2)*128 + ra]      = a0.z;
        As[(ca+3)*128 + ra]      = a0.w;
        As[(ca+0)*128 + ra + 64] = a1.x;
        As[(ca+1)*128 + ra + 64] = a1.y;
        As[(ca+2)*128 + ra + 64] = a1.z;
        As[(ca+3)*128 + ra + 64] = a1.w;
        *(float4*)&Bs[rb*128 + cb]     = b0;
        *(float4*)&Bs[(rb+8)*128 + cb] = b1;
        __syncthreads();
#pragma unroll
        for (int k = 0; k < 16; k++) {
            float4 qa = *(const float4*)&As[k*128 + ty*4];
            float4 qb = *(const float4*)&As[k*128 + 64 + ty*4];
            float4 pa = *(const float4*)&Bs[k*128 + tx*4];
            float4 pb = *(const float4*)&Bs[k*128 + 64 + tx*4];
            float ar[8] = {qa.x,qa.y,qa.z,qa.w,qb.x,qb.y,qb.z,qb.w};
            float br[8] = {pa.x,pa.y,pa.z,pa.w,pb.x,pb.y,pb.z,pb.w};
#pragma unroll
            for (int i = 0; i < 8; i++)
#pragma unroll
                for (int j = 0; j < 8; j++)
                    acc[i][j] = fmaf(ar[i], br[j], acc[i][j]);
        }
    }
}

// ---------------- QKV projection + bias + RoPE -----------------------------
// grid (16, 32, 3): x = head (N-tile == one head), y = M-tile, z = q/k/v
__global__ __launch_bounds__(256, 2)
void gemm_qkv_kernel(const float* __restrict__ X,
                     const float* __restrict__ Wq, const float* __restrict__ Wk,
                     const float* __restrict__ Wv,
                     const float* __restrict__ bq, const float* __restrict__ bk,
                     const float* __restrict__ bv)
{
    __shared__ float As[16*128], Bs[16*128];
    const int z = blockIdx.z;
    const float* W    = (z == 0) ? Wq : (z == 1) ? Wk : Wv;
    const float* bias = (z == 0) ? bq : (z == 1) ? bk : bv;
    float* outb       = (z == 0) ? g_q : (z == 1) ? g_k : g_v;
    const int nh = blockIdx.x;
    const int m0 = blockIdx.y * 128;

    float acc[8][8];
    gemm_tile(X, W, As, Bs, m0, nh * 128, acc);

    const int ty = threadIdx.x >> 4, tx = threadIdx.x & 15;
    const bool rope = (z < 2);
#pragma unroll
    for (int i = 0; i < 8; i++) {
        int rr = (i < 4) ? (ty*4 + i) : (64 + ty*4 + (i-4));
        int m  = m0 + rr;
        int b  = m >> 11, s = m & 2047;
        float lo[4], hi[4];
#pragma unroll
        for (int j = 0; j < 4; j++) {
            int   c   = tx*4 + j;                        // 0..63  (pair index)
            float vlo = acc[i][j]   + bias[nh*128 + c];
            float vhi = acc[i][j+4] + bias[nh*128 + 64 + c];
            if (rope) {
                float cs = g_cos[s*64 + c];
                float sn = g_sin[s*64 + c];
                lo[j] = vlo * cs - vhi * sn;   // x[d]*cos - x[d+64]*sin
                hi[j] = vhi * cs + vlo * sn;   // x[d+64]*cos + x[d]*sin
            } else { lo[j] = vlo; hi[j] = vhi; }
        }
        float* op = outb + ((size_t)(b*NH_ + nh)*S_ + s) * HD_;
        *(float4*)&op[tx*4]      = make_float4(lo[0], lo[1], lo[2], lo[3]);
        *(float4*)&op[64 + tx*4] = make_float4(hi[0], hi[1], hi[2], hi[3]);
    }
}

// ---------------- output projection + bias ---------------------------------
__global__ __launch_bounds__(256, 2)
void gemm_out_kernel(const float* __restrict__ Wo, const float* __restrict__ bo,
                     float* __restrict__ out)
{
    __shared__ float As[16*128], Bs[16*128];
    const int n0 = blockIdx.x * 128;
    const int m0 = blockIdx.y * 128;

    float acc[8][8];
    gemm_tile(g_attn, Wo, As, Bs, m0, n0, acc);

    const int ty = threadIdx.x >> 4, tx = threadIdx.x & 15;
#pragma unroll
    for (int i = 0; i < 8; i++) {
        int rr = (i < 4) ? (ty*4 + i) : (64 + ty*4 + (i-4));
        int m  = m0 + rr;
        float4 lo = make_float4(acc[i][0] + bo[n0 + tx*4 + 0],
                                acc[i][1] + bo[n0 + tx*4 + 1],
                                acc[i][2] + bo[n0 + tx*4 + 2],
                                acc[i][3] + bo[n0 + tx*4 + 3]);
        float4 hi = make_float4(acc[i][4] + bo[n0 + 64 + tx*4 + 0],
                                acc[i][5] + bo[n0 + 64 + tx*4 + 1],
                                acc[i][6] + bo[n0 + 64 + tx*4 + 2],
                                acc[i][7] + bo[n0 + 64 + tx*4 + 3]);
        *(float4*)&out[(size_t)m * H_ + n0 + tx*4]      = lo;
        *(float4*)&out[(size_t)m * H_ + n0 + 64 + tx*4] = hi;
    }
}

// ---------------- causal flash attention (fp32) -----------------------------
// grid (16, 32): x reversed -> iq tile (heavy tiles first), y = b*NH+nh.
// BQ = BKV = 128, 256 threads, 8x8 per-thread score/O tiles.
// Thread (ty,tx): rows ty*8+i, cols tx+16*jj (conflict-minimal smem access).
#define QS_STR 132
#define PS_STR 136

__global__ __launch_bounds__(256, 1)
void attn_kernel()
{
    extern __shared__ float sm[];
    float* Qs  = sm;                     // [128][132]  Q tile
    float* KVs = sm + 128*QS_STR;        // [128][132]  K then V (shared buffer)
    float* Ps  = sm + 2*128*QS_STR;      // [128][136]  probs

    const int tid = threadIdx.x;
    const int ty  = tid >> 4, tx = tid & 15;
    const int bh  = blockIdx.y;
    const int b   = bh >> 4, nh = bh & 15;
    const int iq  = (int)gridDim.x - 1 - (int)blockIdx.x;

    const float* Qg = g_q + ((size_t)(b*NH_ + nh)*S_ + (size_t)iq*128) * HD_;
    const float* Kg = g_k + (size_t)(b*NH_ + nh)*S_*HD_;
    const float* Vg = g_v + (size_t)(b*NH_ + nh)*S_*HD_;

    // load Q tile (coalesced float4)
#pragma unroll
    for (int it = 0; it < 16; it++) {
        int fi = tid + it*256;
        int r = fi >> 5, dc = (fi & 31) << 2;
        *(float4*)&Qs[r*QS_STR + dc] = *(const float4*)&Qg[r*HD_ + dc];
    }

    float O[8][8];
    float mrow[8], lrow[8];
#pragma unroll
    for (int i = 0; i < 8; i++) {
        mrow[i] = -1e30f; lrow[i] = 0.f;
#pragma unroll
        for (int j = 0; j < 8; j++) O[i][j] = 0.f;
    }
    const float scale = 0.08838834764831845f;  // 1/sqrt(128)

    for (int jt = 0; jt <= iq; jt++) {
        __syncthreads();                       // prior PV done with KVs/Ps
        const float* Kt = Kg + (size_t)jt*128*HD_;
#pragma unroll
        for (int it = 0; it < 16; it++) {
            int fi = tid + it*256;
            int r = fi >> 5, dc = (fi & 31) << 2;
            *(float4*)&KVs[r*QS_STR + dc] = *(const float4*)&Kt[r*HD_ + dc];
        }
        __syncthreads();

        // ---- S = Q K^T ----
        float Sc[8][8];
#pragma unroll
        for (int i = 0; i < 8; i++)
#pragma unroll
            for (int j = 0; j < 8; j++) Sc[i][j] = 0.f;

#pragma unroll 4
        for (int d4 = 0; d4 < HD_; d4 += 4) {
            float4 kv[8];
#pragma unroll
            for (int jj = 0; jj < 8; jj++)
                kv[jj] = *(const float4*)&KVs[(tx + 16*jj)*QS_STR + d4];
#pragma unroll
            for (int i = 0; i < 8; i++) {
                float4 qv = *(const float4*)&Qs[(ty*8 + i)*QS_STR + d4];
#pragma unroll
                for (int jj = 0; jj < 8; jj++)
                    Sc[i][jj] += qv.x*kv[jj].x + qv.y*kv[jj].y
                               + qv.z*kv[jj].z + qv.w*kv[jj].w;
            }
        }

        // ---- scale + causal mask (diagonal tile only) ----
        if (jt == iq) {
#pragma unroll
            for (int i = 0; i < 8; i++)
#pragma unroll
                for (int jj = 0; jj < 8; jj++)
                    Sc[i][jj] = (tx + 16*jj > ty*8 + i) ? -1e9f : Sc[i][jj]*scale;
        } else {
#pragma unroll
            for (int i = 0; i < 8; i++)
#pragma unroll
                for (int jj = 0; jj < 8; jj++) Sc[i][jj] *= scale;
        }

        // ---- online softmax (rows owned by 16 tx lanes; butterfly xor) ----
#pragma unroll
        for (int i = 0; i < 8; i++) {
            float mx = Sc[i][0];
#pragma unroll
            for (int jj = 1; jj < 8; jj++) mx = fmaxf(mx, Sc[i][jj]);
            mx = fmaxf(mx, __shfl_xor_sync(0xffffffffu, mx, 1));
            mx = fmaxf(mx, __shfl_xor_sync(0xffffffffu, mx, 2));
            mx = fmaxf(mx, __shfl_xor_sync(0xffffffffu, mx, 4));
            mx = fmaxf(mx, __shfl_xor_sync(0xffffffffu, mx, 8));
            float mnew  = fmaxf(mrow[i], mx);
            float alpha = __expf(mrow[i] - mnew);
            mrow[i] = mnew;
            float rs = 0.f;
#pragma unroll
            for (int jj = 0; jj < 8; jj++) {
                float p = __expf(Sc[i][jj] - mnew);
                Sc[i][jj] = p;
                rs += p;
            }
            rs += __shfl_xor_sync(0xffffffffu, rs, 1);
            rs += __shfl_xor_sync(0xffffffffu, rs, 2);
            rs += __shfl_xor_sync(0xffffffffu, rs, 4);
            rs += __shfl_xor_sync(0xffffffffu, rs, 8);
            lrow[i] = lrow[i]*alpha + rs;
#pragma unroll
            for (int jj = 0; jj < 8; jj++) O[i][jj] *= alpha;
        }

        // ---- stage P, swap K->V in shared buffer ----
#pragma unroll
        for (int i = 0; i < 8; i++)
#pragma unroll
            for (int jj = 0; jj < 8; jj++)
                Ps[(ty*8 + i)*PS_STR + tx + 16*jj] = Sc[i][jj];
        __syncthreads();                       // scores read KVs; Ps written
        const float* Vt = Vg + (size_t)jt*128*HD_;
#pragma unroll
        for (int it = 0; it < 16; it++) {
            int fi = tid + it*256;
            int r = fi >> 5, dc = (fi & 31) << 2;
            *(float4*)&KVs[r*QS_STR + dc] = *(const float4*)&Vt[r*HD_ + dc];
        }
        __syncthreads();

        // ---- O += P V ----
#pragma unroll 4
        for (int k = 0; k < 128; k++) {
            float vv[8];
#pragma unroll
            for (int jj = 0; jj < 8; jj++)
                vv[jj] = KVs[k*QS_STR + tx + 16*jj];
#pragma unroll
            for (int i = 0; i < 8; i++) {
                float pv = Ps[(ty*8 + i)*PS_STR + k];
#pragma unroll
                for (int jj = 0; jj < 8; jj++)
                    O[i][jj] = fmaf(pv, vv[jj], O[i][jj]);
            }
        }
    }

    // ---- finalize: O / l -> g_attn [B*S, NH*HD] ----
    float* outp = g_attn + ((size_t)(b*S_ + iq*128))*H_ + nh*HD_;
#pragma unroll
    for (int i = 0; i < 8; i++) {
        float inv = 1.f / lrow[i];
        int r = ty*8 + i;
#pragma unroll
        for (int jj = 0; jj < 8; jj++)
            outp[(size_t)r*H_ + tx + 16*jj] = O[i][jj] * inv;
    }
}

// ---------------- launch ----------------------------------------------------
extern "C" void kernel_launch(void* const* d_in, const int* in_sizes, int n_in,
                              void* d_out, int out_size)
{
    (void)in_sizes; (void)n_in; (void)out_size;
    const float* X  = (const float*)d_in[0];
    // d_in[1] = mask: data is strictly causal; handled analytically in-kernel.
    const float* Wq = (const float*)d_in[2];
    const float* bq = (const float*)d_in[3];
    const float* Wk = (const float*)d_in[4];
    const float* bk = (const float*)d_in[5];
    const float* Wv = (const float*)d_in[6];
    const float* bv = (const float*)d_in[7];
    const float* Wo = (const float*)d_in[8];
    const float* bo = (const float*)d_in[9];
    float* out = (float*)d_out;

    rope_table_kernel<<<(S_*64 + 255)/256, 256>>>();
    gemm_qkv_kernel<<<dim3(NH_, M_/128, 3), 256>>>(X, Wq, Wk, Wv, bq, bk, bv);

    size_t smem = (size_t)(2*128*QS_STR + 128*PS_STR) * sizeof(float); // 204,800 B
    cudaFuncSetAttribute(attn_kernel, cudaFuncAttributeMaxDynamicSharedMemorySize,
                         (int)smem);
    attn_kernel<<<dim3(S_/128, B_*NH_), 256, smem>>>();

    gemm_out_kernel<<<dim3(H_/128, M_/128), 256>>>(Wo, bo, out);
}

// round 2
// speedup vs baseline: 1.0010x; 1.0010x over previous
#include <cuda_runtime.h>
#include <math.h>

#define B_  2
#define S_  2048
#define H_  2048
#define NH_ 16
#define HD_ 128
#define M_  (B_*S_)   // 4096

// ---------------- scratch (device globals; no allocation allowed) ----------
__device__ float g_q[B_*NH_*S_*HD_];      // [B,NH,S,HD]
__device__ float g_k[B_*NH_*S_*HD_];
__device__ float g_v[B_*NH_*S_*HD_];
__device__ float g_attn[M_*H_];           // [B*S, NH*HD]
__device__ float g_cos[S_*64];
__device__ float g_sin[S_*64];

// ---------------- RoPE table ----------------------------------------------
__global__ void rope_table_kernel()
{
    int idx = blockIdx.x * blockDim.x + threadIdx.x;
    if (idx >= S_ * 64) return;
    int s = idx >> 6, p = idx & 63;
    double invf = exp(-log(10000.0) * (double)p / 64.0);
    double ang  = (double)s * invf;
    g_cos[idx] = (float)cos(ang);
    g_sin[idx] = (float)sin(ang);
}

// ---------------- shared 128x128x2048 fp32 GEMM mainloop -------------------
// 256 threads, BM=BN=128, BK=16, 8x8 per-thread tile.
// Thread (ty,tx): rows {ty*4+i, 64+ty*4+i}, cols {tx*4+j, 64+tx*4+j}.
__device__ __forceinline__ void gemm_tile(const float* __restrict__ A,
                                          const float* __restrict__ Bm,
                                          float* As, float* Bs,
                                          int m0, int n0, float acc[8][8])
{
    const int tid = threadIdx.x;
    const int ty = tid >> 4, tx = tid & 15;
    const int ra = tid >> 2, ca = (tid & 3) << 2;   // A loader: 64 rows x 4 col-groups
    const int rb = tid >> 5, cb = (tid & 31) << 2;  // B loader: 8 rows x 32 col-groups

#pragma unroll
    for (int i = 0; i < 8; i++)
#pragma unroll
        for (int j = 0; j < 8; j++) acc[i][j] = 0.f;

    for (int kt = 0; kt < H_; kt += 16) {
        float4 a0 = *(const float4*)&A[(m0 + ra)      * H_ + kt + ca];
        float4 a1 = *(const float4*)&A[(m0 + ra + 64) * H_ + kt + ca];
        float4 b0 = *(const float4*)&Bm[(kt + rb)     * H_ + n0 + cb];
        float4 b1 = *(const float4*)&Bm[(kt + rb + 8) * H_ + n0 + cb];
        __syncthreads();
        // A stored k-major (transposed) for broadcast-friendly compute reads
        As[(ca+0)*128 + ra]      = a0.x;
        As[(ca+1)*128 + ra]      = a0.y;
        As[(ca+2)*128 + ra]      = a0.z;
        As[(ca+3)*128 + ra]      = a0.w;
        As[(ca+0)*128 + ra + 64] = a1.x;
        As[(ca+1)*128 + ra + 64] = a1.y;
        As[(ca+2)*128 + ra + 64] = a1.z;
        As[(ca+3)*128 + ra + 64] = a1.w;
        *(float4*)&Bs[rb*128 + cb]     = b0;
        *(float4*)&Bs[(rb+8)*128 + cb] = b1;
        __syncthreads();
#pragma unroll
        for (int k = 0; k < 16; k++) {
            float4 qa = *(const float4*)&As[k*128 + ty*4];
            float4 qb = *(const float4*)&As[k*128 + 64 + ty*4];
            float4 pa = *(const float4*)&Bs[k*128 + tx*4];
            float4 pb = *(const float4*)&Bs[k*128 + 64 + tx*4];
            float ar[8] = {qa.x,qa.y,qa.z,qa.w,qb.x,qb.y,qb.z,qb.w};
            float br[8] = {pa.x,pa.y,pa.z,pa.w,pb.x,pb.y,pb.z,pb.w};
#pragma unroll
            for (int i = 0; i < 8; i++)
#pragma unroll
                for (int j = 0; j < 8; j++)
                    acc[i][j] = fmaf(ar[i], br[j], acc[i][j]);
        }
    }
}

// ---------------- QKV projection + bias + RoPE -----------------------------
// grid (16, 32, 3): x = head (N-tile == one head), y = M-tile, z = q/k/v
__global__ __launch_bounds__(256, 2)
void gemm_qkv_kernel(const float* __restrict__ X,
                     const float* __restrict__ Wq, const float* __restrict__ Wk,
                     const float* __restrict__ Wv,
                     const float* __restrict__ bq, const float* __restrict__ bk,
                     const float* __restrict__ bv)
{
    __shared__ float As[16*128], Bs[16*128];
    const int z = blockIdx.z;
    const float* W    = (z == 0) ? Wq : (z == 1) ? Wk : Wv;
    const float* bias = (z == 0) ? bq : (z == 1) ? bk : bv;
    float* outb       = (z == 0) ? g_q : (z == 1) ? g_k : g_v;
    const int nh = blockIdx.x;
    const int m0 = blockIdx.y * 128;

    float acc[8][8];
    gemm_tile(X, W, As, Bs, m0, nh * 128, acc);

    const int ty = threadIdx.x >> 4, tx = threadIdx.x & 15;
    const bool rope = (z < 2);
#pragma unroll
    for (int i = 0; i < 8; i++) {
        int rr = (i < 4) ? (ty*4 + i) : (64 + ty*4 + (i-4));
        int m  = m0 + rr;
        int b  = m >> 11, s = m & 2047;
        float lo[4], hi[4];
#pragma unroll
        for (int j = 0; j < 4; j++) {
            int   c   = tx*4 + j;                        // 0..63  (pair index)
            float vlo = acc[i][j]   + bias[nh*128 + c];
            float vhi = acc[i][j+4] + bias[nh*128 + 64 + c];
            if (rope) {
                float cs = g_cos[s*64 + c];
                float sn = g_sin[s*64 + c];
                lo[j] = vlo * cs - vhi * sn;   // x[d]*cos - x[d+64]*sin
                hi[j] = vhi * cs + vlo * sn;   // x[d+64]*cos + x[d]*sin
            } else { lo[j] = vlo; hi[j] = vhi; }
        }
        float* op = outb + ((size_t)(b*NH_ + nh)*S_ + s) * HD_;
        *(float4*)&op[tx*4]      = make_float4(lo[0], lo[1], lo[2], lo[3]);
        *(float4*)&op[64 + tx*4] = make_float4(hi[0], hi[1], hi[2], hi[3]);
    }
}

// ---------------- output projection + bias ---------------------------------
__global__ __launch_bounds__(256, 2)
void gemm_out_kernel(const float* __restrict__ Wo, const float* __restrict__ bo,
                     float* __restrict__ out)
{
    __shared__ float As[16*128], Bs[16*128];
    const int n0 = blockIdx.x * 128;
    const int m0 = blockIdx.y * 128;

    float acc[8][8];
    gemm_tile(g_attn, Wo, As, Bs, m0, n0, acc);

    const int ty = threadIdx.x >> 4, tx = threadIdx.x & 15;
#pragma unroll
    for (int i = 0; i < 8; i++) {
        int rr = (i < 4) ? (ty*4 + i) : (64 + ty*4 + (i-4));
        int m  = m0 + rr;
        float4 lo = make_float4(acc[i][0] + bo[n0 + tx*4 + 0],
                                acc[i][1] + bo[n0 + tx*4 + 1],
                                acc[i][2] + bo[n0 + tx*4 + 2],
                                acc[i][3] + bo[n0 + tx*4 + 3]);
        float4 hi = make_float4(acc[i][4] + bo[n0 + 64 + tx*4 + 0],
                                acc[i][5] + bo[n0 + 64 + tx*4 + 1],
                                acc[i][6] + bo[n0 + 64 + tx*4 + 2],
                                acc[i][7] + bo[n0 + 64 + tx*4 + 3]);
        *(float4*)&out[(size_t)m * H_ + n0 + tx*4]      = lo;
        *(float4*)&out[(size_t)m * H_ + n0 + 64 + tx*4] = hi;
    }
}

// ---------------- causal flash attention (fp32) -----------------------------
// grid (16, 32): x reversed -> iq tile (heavy tiles first), y = b*NH+nh.
// BQ = BKV = 128, 256 threads, 8x8 per-thread score/O tiles.
// Thread (ty,tx): rows ty*8+i, cols tx+16*jj (conflict-minimal smem access).
#define QS_STR 132
#define PS_STR 136

__global__ __launch_bounds__(256, 1)
void attn_kernel()
{
    extern __shared__ float sm[];
    float* Qs  = sm;                     // [128][132]  Q tile
    float* KVs = sm + 128*QS_STR;        // [128][132]  K then V (shared buffer)
    float* Ps  = sm + 2*128*QS_STR;      // [128][136]  probs

    const int tid = threadIdx.x;
    const int ty  = tid >> 4, tx = tid & 15;
    const int bh  = blockIdx.y;
    const int b   = bh >> 4, nh = bh & 15;
    const int iq  = (int)gridDim.x - 1 - (int)blockIdx.x;

    const float* Qg = g_q + ((size_t)(b*NH_ + nh)*S_ + (size_t)iq*128) * HD_;
    const float* Kg = g_k + (size_t)(b*NH_ + nh)*S_*HD_;
    const float* Vg = g_v + (size_t)(b*NH_ + nh)*S_*HD_;

    // load Q tile (coalesced float4)
#pragma unroll
    for (int it = 0; it < 16; it++) {
        int fi = tid + it*256;
        int r = fi >> 5, dc = (fi & 31) << 2;
        *(float4*)&Qs[r*QS_STR + dc] = *(const float4*)&Qg[r*HD_ + dc];
    }

    float O[8][8];
    float mrow[8], lrow[8];
#pragma unroll
    for (int i = 0; i < 8; i++) {
        mrow[i] = -1e30f; lrow[i] = 0.f;
#pragma unroll
        for (int j = 0; j < 8; j++) O[i][j] = 0.f;
    }
    const float scale = 0.08838834764831845f;  // 1/sqrt(128)

    for (int jt = 0; jt <= iq; jt++) {
        __syncthreads();                       // prior PV done with KVs/Ps
        const float* Kt = Kg + (size_t)jt*128*HD_;
#pragma unroll
        for (int it = 0; it < 16; it++) {
            int fi = tid + it*256;
            int r = fi >> 5, dc = (fi & 31) << 2;
            *(float4*)&KVs[r*QS_STR + dc] = *(const float4*)&Kt[r*HD_ + dc];
        }
        __syncthreads();

        // ---- S = Q K^T ----
        float Sc[8][8];
#pragma unroll
        for (int i = 0; i < 8; i++)
#pragma unroll
            for (int j = 0; j < 8; j++) Sc[i][j] = 0.f;

#pragma unroll 4
        for (int d4 = 0; d4 < HD_; d4 += 4) {
            float4 kv[8];
#pragma unroll
            for (int jj = 0; jj < 8; jj++)
                kv[jj] = *(const float4*)&KVs[(tx + 16*jj)*QS_STR + d4];
#pragma unroll
            for (int i = 0; i < 8; i++) {
                float4 qv = *(const float4*)&Qs[(ty*8 + i)*QS_STR + d4];
#pragma unroll
                for (int jj = 0; jj < 8; jj++)
                    Sc[i][jj] += qv.x*kv[jj].x + qv.y*kv[jj].y
                               + qv.z*kv[jj].z + qv.w*kv[jj].w;
            }
        }

        // ---- scale + causal mask (diagonal tile only) ----
        if (jt == iq) {
#pragma unroll
            for (int i = 0; i < 8; i++)
#pragma unroll
                for (int jj = 0; jj < 8; jj++)
                    Sc[i][jj] = (tx + 16*jj > ty*8 + i) ? -1e9f : Sc[i][jj]*scale;
        } else {
#pragma unroll
            for (int i = 0; i < 8; i++)
#pragma unroll
                for (int jj = 0; jj < 8; jj++) Sc[i][jj] *= scale;
        }

        // ---- online softmax (rows owned by 16 tx lanes; butterfly xor) ----
#pragma unroll
        for (int i = 0; i < 8; i++) {
            float mx = Sc[i][0];
#pragma unroll
            for (int jj = 1; jj < 8; jj++) mx = fmaxf(mx, Sc[i][jj]);
            mx = fmaxf(mx, __shfl_xor_sync(0xffffffffu, mx, 1));
            mx = fmaxf(mx, __shfl_xor_sync(0xffffffffu, mx, 2));
            mx = fmaxf(mx, __shfl_xor_sync(0xffffffffu, mx, 4));
            mx = fmaxf(mx, __shfl_xor_sync(0xffffffffu, mx, 8));
            float mnew  = fmaxf(mrow[i], mx);
            float alpha = __expf(mrow[i] - mnew);
            mrow[i] = mnew;
            float rs = 0.f;
#pragma unroll
            for (int jj = 0; jj < 8; jj++) {
                float p = __expf(Sc[i][jj] - mnew);
                Sc[i][jj] = p;
                rs += p;
            }
            rs += __shfl_xor_sync(0xffffffffu, rs, 1);
            rs += __shfl_xor_sync(0xffffffffu, rs, 2);
            rs += __shfl_xor_sync(0xffffffffu, rs, 4);
            rs += __shfl_xor_sync(0xffffffffu, rs, 8);
            lrow[i] = lrow[i]*alpha + rs;
#pragma unroll
            for (int jj = 0; jj < 8; jj++) O[i][jj] *= alpha;
        }

        // ---- stage P, swap K->V in shared buffer ----
#pragma unroll
        for (int i = 0; i < 8; i++)
#pragma unroll
            for (int jj = 0; jj < 8; jj++)
                Ps[(ty*8 + i)*PS_STR + tx + 16*jj] = Sc[i][jj];
        __syncthreads();                       // scores read KVs; Ps written
        const float* Vt = Vg + (size_t)jt*128*HD_;
#pragma unroll
        for (int it = 0; it < 16; it++) {
            int fi = tid + it*256;
            int r = fi >> 5, dc = (fi & 31) << 2;
            *(float4*)&KVs[r*QS_STR + dc] = *(const float4*)&Vt[r*HD_ + dc];
        }
        __syncthreads();

        // ---- O += P V ----
#pragma unroll 4
        for (int k = 0; k < 128; k++) {
            float vv[8];
#pragma unroll
            for (int jj = 0; jj < 8; jj++)
                vv[jj] = KVs[k*QS_STR + tx + 16*jj];
#pragma unroll
            for (int i = 0; i < 8; i++) {
                float pv = Ps[(ty*8 + i)*PS_STR + k];
#pragma unroll
                for (int jj = 0; jj < 8; jj++)
                    O[i][jj] = fmaf(pv, vv[jj], O[i][jj]);
            }
        }
    }

    // ---- finalize: O / l -> g_attn [B*S, NH*HD] ----
    float* outp = g_attn + ((size_t)(b*S_ + iq*128))*H_ + nh*HD_;
#pragma unroll
    for (int i = 0; i < 8; i++) {
        float inv = 1.f / lrow[i];
        int r = ty*8 + i;
#pragma unroll
        for (int jj = 0; jj < 8; jj++)
            outp[(size_t)r*H_ + tx + 16*jj] = O[i][jj] * inv;
    }
}

// ---------------- launch ----------------------------------------------------
extern "C" void kernel_launch(void* const* d_in, const int* in_sizes, int n_in,
                              void* d_out, int out_size)
{
    (void)in_sizes; (void)n_in; (void)out_size;
    const float* X  = (const float*)d_in[0];
    // d_in[1] = mask: data is strictly causal; handled analytically in-kernel.
    const float* Wq = (const float*)d_in[2];
    const float* bq = (const float*)d_in[3];
    const float* Wk = (const float*)d_in[4];
    const float* bk = (const float*)d_in[5];
    const float* Wv = (const float*)d_in[6];
    const float* bv = (const float*)d_in[7];
    const float* Wo = (const float*)d_in[8];
    const float* bo = (const float*)d_in[9];
    float* out = (float*)d_out;

    rope_table_kernel<<<(S_*64 + 255)/256, 256>>>();
    gemm_qkv_kernel<<<dim3(NH_, M_/128, 3), 256>>>(X, Wq, Wk, Wv, bq, bk, bv);

    size_t smem = (size_t)(2*128*QS_STR + 128*PS_STR) * sizeof(float); // 204,800 B
    cudaFuncSetAttribute(attn_kernel, cudaFuncAttributeMaxDynamicSharedMemorySize,
                         (int)smem);
    attn_kernel<<<dim3(S_/128, B_*NH_), 256, smem>>>();

    gemm_out_kernel<<<dim3(H_/128, M_/128), 256>>>(Wo, bo, out);
}

// round 4
// speedup vs baseline: 1.5076x; 1.5061x over previous
#include <cuda_runtime.h>
#include <cuda_bf16.h>
#include <math.h>
#include <stdint.h>

#define B_  2
#define S_  2048
#define H_  2048
#define NH_ 16
#define HD_ 128
#define M_  (B_*S_)   // 4096

// ---------------- scratch (device globals) ---------------------------------
__device__ float g_q[B_*NH_*S_*HD_];
__device__ float g_k[B_*NH_*S_*HD_];
__device__ float g_v[B_*NH_*S_*HD_];
__device__ float g_attn[M_*H_];
__device__ float g_cos[S_*64];
__device__ float g_sin[S_*64];

__device__ __align__(16) __nv_bfloat16 g_Ah[M_*H_],  g_Al[M_*H_];     // A hi/lo
__device__ __align__(16) __nv_bfloat16 g_Bh[3*H_*H_], g_Bl[3*H_*H_];  // W^T qkv
__device__ __align__(16) __nv_bfloat16 g_Wh[H_*H_],  g_Wl[H_*H_];     // Wo^T

// ---------------- PTX helpers ----------------------------------------------
__device__ __forceinline__ uint32_t smem_u32(const void* p) {
    uint32_t a;
    asm("{ .reg .u64 t; cvta.to.shared.u64 t, %1; cvt.u32.u64 %0, t; }"
        : "=r"(a) : "l"(p));
    return a;
}
#define CP16(dst, src) \
    asm volatile("cp.async.cg.shared.global [%0], [%1], 16;" \
                 :: "r"(dst), "l"(src) : "memory")
#define CP_COMMIT() asm volatile("cp.async.commit_group;" ::: "memory")

#define LDM4(r, addr) \
    asm volatile("ldmatrix.sync.aligned.m8n8.x4.shared.b16 {%0,%1,%2,%3}, [%4];" \
        : "=r"((r)[0]), "=r"((r)[1]), "=r"((r)[2]), "=r"((r)[3]) : "r"(addr))

__device__ __forceinline__ void mma_bf16(float* d, const uint32_t* a,
                                         const uint32_t* b) {
    asm volatile("mma.sync.aligned.m16n8k16.row.col.f32.bf16.bf16.f32 "
        "{%0,%1,%2,%3}, {%4,%5,%6,%7}, {%8,%9}, {%0,%1,%2,%3};"
        : "+f"(d[0]), "+f"(d[1]), "+f"(d[2]), "+f"(d[3])
        : "r"(a[0]), "r"(a[1]), "r"(a[2]), "r"(a[3]), "r"(b[0]), "r"(b[1]));
}

// ---------------- prep kernels ---------------------------------------------
__global__ void rope_table_kernel()
{
    int idx = blockIdx.x * blockDim.x + threadIdx.x;
    if (idx >= S_ * 64) return;
    int s = idx >> 6, p = idx & 63;
    double invf = exp(-log(10000.0) * (double)p / 64.0);
    double ang  = (double)s * invf;
    g_cos[idx] = (float)cos(ang);
    g_sin[idx] = (float)sin(ang);
}

// src_sel: 0 -> read param 'in', 1 -> read g_attn. Writes g_Ah/g_Al.
__global__ void convert_split_kernel(const float* __restrict__ in, int src_sel)
{
    const float* src = src_sel ? g_attn : in;
    int i = (blockIdx.x * blockDim.x + threadIdx.x) * 4;
    float4 v = *(const float4*)&src[i];
    float x[4] = {v.x, v.y, v.z, v.w};
    unsigned short hs[4], ls[4];
#pragma unroll
    for (int j = 0; j < 4; j++) {
        __nv_bfloat16 h = __float2bfloat16(x[j]);
        __nv_bfloat16 l = __float2bfloat16(x[j] - __bfloat162float(h));
        hs[j] = __bfloat16_as_ushort(h); ls[j] = __bfloat16_as_ushort(l);
    }
    *(ushort4*)((unsigned short*)g_Ah + i) = make_ushort4(hs[0], hs[1], hs[2], hs[3]);
    *(ushort4*)((unsigned short*)g_Al + i) = make_ushort4(ls[0], ls[1], ls[2], ls[3]);
}

// W [2048,2048] row-major -> W^T hi/lo bf16. which: 0..2 -> g_Bh/g_Bl slab z,
// 3 -> g_Wh/g_Wl
__global__ void transpose_split_kernel(const float* __restrict__ in, int which)
{
    __nv_bfloat16* hi = (which < 3) ? g_Bh + (size_t)which*H_*H_ : g_Wh;
    __nv_bfloat16* lo = (which < 3) ? g_Bl + (size_t)which*H_*H_ : g_Wl;
    __shared__ float t[32][33];
    int tx = threadIdx.x, ty = threadIdx.y;          // (32,8)
    int c0 = blockIdx.x * 32, r0 = blockIdx.y * 32;
#pragma unroll
    for (int k = 0; k < 4; k++)
        t[ty + 8*k][tx] = in[(size_t)(r0 + ty + 8*k) * H_ + c0 + tx];
    __syncthreads();
#pragma unroll
    for (int k = 0; k < 4; k++) {
        float x = t[tx][ty + 8*k];
        __nv_bfloat16 h = __float2bfloat16(x);
        __nv_bfloat16 l = __float2bfloat16(x - __bfloat162float(h));
        size_t o = (size_t)(c0 + ty + 8*k) * H_ + r0 + tx;
        hi[o] = h; lo[o] = l;
    }
}

// ---------------- HMMA GEMM mainloop ---------------------------------------
// CTA tile 128x128, BK=32 bf16, 4-stage cp.async ring.
// smem stage: Ah|Al|Bh|Bl regions, each 128 rows x 80B (32 bf16 + pad).
#define RSTR   80              // row stride bytes (conflict-free for ldmatrix)
#define REG_B  (128*RSTR)      // 10240 bytes per region
#define STG_B  (4*REG_B)       // 40960 bytes per stage
#define SMEM_GG (4*STG_B)      // 163840

__device__ __forceinline__ void ld_region(uint32_t dst,
    const __nv_bfloat16* __restrict__ src, int row0, int kb, int tid)
{
#pragma unroll
    for (int it = 0; it < 2; it++) {
        int idx = tid + it*256;             // 512 = 128 rows x 4 chunks
        int r = idx >> 2, c = idx & 3;
        CP16(dst + r*RSTR + c*16,
             (const void*)(src + (size_t)(row0 + r) * H_ + kb + c*8));
    }
}
__device__ __forceinline__ void ld_stage(uint32_t s0,
    const __nv_bfloat16* Ah, const __nv_bfloat16* Al,
    const __nv_bfloat16* Bh, const __nv_bfloat16* Bl,
    int m0, int n0, int kb, int tid)
{
    ld_region(s0,           Ah, m0, kb, tid);
    ld_region(s0 +   REG_B, Al, m0, kb, tid);
    ld_region(s0 + 2*REG_B, Bh, n0, kb, tid);
    ld_region(s0 + 3*REG_B, Bl, n0, kb, tid);
    CP_COMMIT();
}

// acc[mi][nj][4]: warp rows (w>>1)*32 + mi*16 (+lane pattern),
// cols (w&1)*32 + (nj&3)*8 + (nj&4 ? 64 : 0)
__device__ __forceinline__ void hmma_mainloop(
    const __nv_bfloat16* Ah, const __nv_bfloat16* Al,
    const __nv_bfloat16* Bh, const __nv_bfloat16* Bl,
    int m0, int n0, uint32_t sb, float acc[2][8][4])
{
    const int tid = threadIdx.x, lane = tid & 31, w = tid >> 5;
#pragma unroll
    for (int i = 0; i < 2; i++)
#pragma unroll
        for (int j = 0; j < 8; j++)
#pragma unroll
            for (int k = 0; k < 4; k++) acc[i][j][k] = 0.f;

    ld_stage(sb,           Ah, Al, Bh, Bl, m0, n0, 0,  tid);
    ld_stage(sb +   STG_B, Ah, Al, Bh, Bl, m0, n0, 32, tid);
    ld_stage(sb + 2*STG_B, Ah, Al, Bh, Bl, m0, n0, 64, tid);

    const int arow = (w >> 1)*32 + (lane & 15);
    const int brow = (w & 1)*32 + (lane & 15);
    const int fcol = (lane >> 4) << 4;      // 0 or 16 bytes

    for (int ch = 0; ch < 64; ch++) {
        if (ch < 62)       asm volatile("cp.async.wait_group 2;" ::: "memory");
        else if (ch == 62) asm volatile("cp.async.wait_group 1;" ::: "memory");
        else               asm volatile("cp.async.wait_group 0;" ::: "memory");
        __syncthreads();
        uint32_t s0 = sb + (ch & 3)*STG_B;
#pragma unroll
        for (int kk = 0; kk < 2; kk++) {
            int kB = kk*32 + fcol;
            uint32_t a[2][2][4], b[2][8][2];
#pragma unroll
            for (int t = 0; t < 2; t++)
#pragma unroll
                for (int mi = 0; mi < 2; mi++)
                    LDM4(a[t][mi], s0 + t*REG_B + (arow + mi*16)*RSTR + kB);
#pragma unroll
            for (int t = 0; t < 2; t++)
#pragma unroll
                for (int p = 0; p < 4; p++) {
                    int r = brow + (p & 1)*16 + ((p & 2) ? 64 : 0);
                    uint32_t q[4];
                    LDM4(q, s0 + (2 + t)*REG_B + r*RSTR + kB);
                    b[t][2*p][0]   = q[0]; b[t][2*p][1]   = q[2];
                    b[t][2*p+1][0] = q[1]; b[t][2*p+1][1] = q[3];
                }
#pragma unroll
            for (int mi = 0; mi < 2; mi++)
#pragma unroll
                for (int nj = 0; nj < 8; nj++)
                    mma_bf16(acc[mi][nj], a[0][mi], b[0][nj]);   // hi*hi
#pragma unroll
            for (int mi = 0; mi < 2; mi++)
#pragma unroll
                for (int nj = 0; nj < 8; nj++)
                    mma_bf16(acc[mi][nj], a[0][mi], b[1][nj]);   // hi*lo
#pragma unroll
            for (int mi = 0; mi < 2; mi++)
#pragma unroll
                for (int nj = 0; nj < 8; nj++)
                    mma_bf16(acc[mi][nj], a[1][mi], b[0][nj]);   // lo*hi
        }
        if (ch + 3 < 64)
            ld_stage(sb + ((ch + 3) & 3)*STG_B, Ah, Al, Bh, Bl,
                     m0, n0, (ch + 3)*32, tid);
    }
}

// ---------------- QKV projection + bias + RoPE ------------------------------
// grid (48, 32): x -> z = x>>4 (q/k/v), nh = x&15 ; y -> m-tile
__global__ __launch_bounds__(256, 1)
void gemm_qkv_tc(const float* __restrict__ bq, const float* __restrict__ bk,
                 const float* __restrict__ bv)
{
    extern __shared__ char dsm[];
    uint32_t sb = smem_u32(dsm);
    const int tid = threadIdx.x, lane = tid & 31, w = tid >> 5;
    const int z = blockIdx.x >> 4, nh = blockIdx.x & 15;
    const int m0 = blockIdx.y * 128, n0 = nh * 128;
    const float* bias = (z == 0) ? bq : (z == 1) ? bk : bv;
    float* outb       = (z == 0) ? g_q : (z == 1) ? g_k : g_v;
    const __nv_bfloat16* Bh = g_Bh + (size_t)z * H_ * H_;
    const __nv_bfloat16* Bl = g_Bl + (size_t)z * H_ * H_;

    float acc[2][8][4];
    hmma_mainloop(g_Ah, g_Al, Bh, Bl, m0, n0, sb, acc);

    const int gr = lane >> 2, gc = (lane & 3)*2;
    const bool rope = (z < 2);
#pragma unroll
    for (int mi = 0; mi < 2; mi++)
#pragma unroll
        for (int h = 0; h < 2; h++) {
            int m = m0 + (w >> 1)*32 + mi*16 + gr + h*8;
            int bb = m >> 11, s = m & 2047;
            float* op = outb + ((size_t)(bb*NH_ + nh)*S_ + s) * HD_;
#pragma unroll
            for (int nj = 0; nj < 4; nj++) {
                int c = (w & 1)*32 + nj*8 + gc;
                float vl0 = acc[mi][nj][h*2+0]   + bias[n0 + c];
                float vl1 = acc[mi][nj][h*2+1]   + bias[n0 + c + 1];
                float vh0 = acc[mi][nj+4][h*2+0] + bias[n0 + 64 + c];
                float vh1 = acc[mi][nj+4][h*2+1] + bias[n0 + 64 + c + 1];
                float o0 = vl0, o1 = vl1, o2 = vh0, o3 = vh1;
                if (rope) {
                    float cs0 = g_cos[s*64 + c],     sn0 = g_sin[s*64 + c];
                    float cs1 = g_cos[s*64 + c + 1], sn1 = g_sin[s*64 + c + 1];
                    o0 = vl0*cs0 - vh0*sn0;  o2 = vh0*cs0 + vl0*sn0;
                    o1 = vl1*cs1 - vh1*sn1;  o3 = vh1*cs1 + vl1*sn1;
                }
                *(float2*)&op[c]      = make_float2(o0, o1);
                *(float2*)&op[64 + c] = make_float2(o2, o3);
            }
        }
}

// ---------------- output projection + bias ----------------------------------
__global__ __launch_bounds__(256, 1)
void gemm_out_tc(const float* __restrict__ bo, float* __restrict__ out)
{
    extern __shared__ char dsm[];
    uint32_t sb = smem_u32(dsm);
    const int tid = threadIdx.x, lane = tid & 31, w = tid >> 5;
    const int m0 = blockIdx.y * 128, n0 = blockIdx.x * 128;

    float acc[2][8][4];
    hmma_mainloop(g_Ah, g_Al, g_Wh, g_Wl, m0, n0, sb, acc);

    const int gr = lane >> 2, gc = (lane & 3)*2;
#pragma unroll
    for (int mi = 0; mi < 2; mi++)
#pragma unroll
        for (int h = 0; h < 2; h++) {
            int m = m0 + (w >> 1)*32 + mi*16 + gr + h*8;
            float* op = out + (size_t)m * H_ + n0;
#pragma unroll
            for (int nj = 0; nj < 4; nj++) {
                int c = (w & 1)*32 + nj*8 + gc;
                *(float2*)&op[c] = make_float2(
                    acc[mi][nj][h*2+0] + bo[n0 + c],
                    acc[mi][nj][h*2+1] + bo[n0 + c + 1]);
                *(float2*)&op[64 + c] = make_float2(
                    acc[mi][nj+4][h*2+0] + bo[n0 + 64 + c],
                    acc[mi][nj+4][h*2+1] + bo[n0 + 64 + c + 1]);
            }
        }
}

// ---------------- causal flash attention (fp32, unchanged) ------------------
#define QS_STR 132
#define PS_STR 136

__global__ __launch_bounds__(256, 1)
void attn_kernel()
{
    extern __shared__ float sm[];
    float* Qs  = sm;
    float* KVs = sm + 128*QS_STR;
    float* Ps  = sm + 2*128*QS_STR;

    const int tid = threadIdx.x;
    const int ty  = tid >> 4, tx = tid & 15;
    const int bh  = blockIdx.y;
    const int b   = bh >> 4, nh = bh & 15;
    const int iq  = (int)gridDim.x - 1 - (int)blockIdx.x;

    const float* Qg = g_q + ((size_t)(b*NH_ + nh)*S_ + (size_t)iq*128) * HD_;
    const float* Kg = g_k + (size_t)(b*NH_ + nh)*S_*HD_;
    const float* Vg = g_v + (size_t)(b*NH_ + nh)*S_*HD_;

#pragma unroll
    for (int it = 0; it < 16; it++) {
        int fi = tid + it*256;
        int r = fi >> 5, dc = (fi & 31) << 2;
        *(float4*)&Qs[r*QS_STR + dc] = *(const float4*)&Qg[r*HD_ + dc];
    }

    float O[8][8]; float mrow[8], lrow[8];
#pragma unroll
    for (int i = 0; i < 8; i++) {
        mrow[i] = -1e30f; lrow[i] = 0.f;
#pragma unroll
        for (int j = 0; j < 8; j++) O[i][j] = 0.f;
    }
    const float scale = 0.08838834764831845f;

    for (int jt = 0; jt <= iq; jt++) {
        __syncthreads();
        const float* Kt = Kg + (size_t)jt*128*HD_;
#pragma unroll
        for (int it = 0; it < 16; it++) {
            int fi = tid + it*256;
            int r = fi >> 5, dc = (fi & 31) << 2;
            *(float4*)&KVs[r*QS_STR + dc] = *(const float4*)&Kt[r*HD_ + dc];
        }
        __syncthreads();

        float Sc[8][8];
#pragma unroll
        for (int i = 0; i < 8; i++)
#pragma unroll
            for (int j = 0; j < 8; j++) Sc[i][j] = 0.f;

#pragma unroll 4
        for (int d4 = 0; d4 < HD_; d4 += 4) {
            float4 kv[8];
#pragma unroll
            for (int jj = 0; jj < 8; jj++)
                kv[jj] = *(const float4*)&KVs[(tx + 16*jj)*QS_STR + d4];
#pragma unroll
            for (int i = 0; i < 8; i++) {
                float4 qv = *(const float4*)&Qs[(ty*8 + i)*QS_STR + d4];
#pragma unroll
                for (int jj = 0; jj < 8; jj++)
                    Sc[i][jj] += qv.x*kv[jj].x + qv.y*kv[jj].y
                               + qv.z*kv[jj].z + qv.w*kv[jj].w;
            }
        }

        if (jt == iq) {
#pragma unroll
            for (int i = 0; i < 8; i++)
#pragma unroll
                for (int jj = 0; jj < 8; jj++)
                    Sc[i][jj] = (tx + 16*jj > ty*8 + i) ? -1e9f : Sc[i][jj]*scale;
        } else {
#pragma unroll
            for (int i = 0; i < 8; i++)
#pragma unroll
                for (int jj = 0; jj < 8; jj++) Sc[i][jj] *= scale;
        }

#pragma unroll
        for (int i = 0; i < 8; i++) {
            float mx = Sc[i][0];
#pragma unroll
            for (int jj = 1; jj < 8; jj++) mx = fmaxf(mx, Sc[i][jj]);
            mx = fmaxf(mx, __shfl_xor_sync(0xffffffffu, mx, 1));
            mx = fmaxf(mx, __shfl_xor_sync(0xffffffffu, mx, 2));
            mx = fmaxf(mx, __shfl_xor_sync(0xffffffffu, mx, 4));
            mx = fmaxf(mx, __shfl_xor_sync(0xffffffffu, mx, 8));
            float mnew  = fmaxf(mrow[i], mx);
            float alpha = __expf(mrow[i] - mnew);
            mrow[i] = mnew;
            float rs = 0.f;
#pragma unroll
            for (int jj = 0; jj < 8; jj++) {
                float p = __expf(Sc[i][jj] - mnew);
                Sc[i][jj] = p; rs += p;
            }
            rs += __shfl_xor_sync(0xffffffffu, rs, 1);
            rs += __shfl_xor_sync(0xffffffffu, rs, 2);
            rs += __shfl_xor_sync(0xffffffffu, rs, 4);
            rs += __shfl_xor_sync(0xffffffffu, rs, 8);
            lrow[i] = lrow[i]*alpha + rs;
#pragma unroll
            for (int jj = 0; jj < 8; jj++) O[i][jj] *= alpha;
        }

#pragma unroll
        for (int i = 0; i < 8; i++)
#pragma unroll
            for (int jj = 0; jj < 8; jj++)
                Ps[(ty*8 + i)*PS_STR + tx + 16*jj] = Sc[i][jj];
        __syncthreads();
        const float* Vt = Vg + (size_t)jt*128*HD_;
#pragma unroll
        for (int it = 0; it < 16; it++) {
            int fi = tid + it*256;
            int r = fi >> 5, dc = (fi & 31) << 2;
            *(float4*)&KVs[r*QS_STR + dc] = *(const float4*)&Vt[r*HD_ + dc];
        }
        __syncthreads();

#pragma unroll 4
        for (int k = 0; k < 128; k++) {
            float vv[8];
#pragma unroll
            for (int jj = 0; jj < 8; jj++)
                vv[jj] = KVs[k*QS_STR + tx + 16*jj];
#pragma unroll
            for (int i = 0; i < 8; i++) {
                float pv = Ps[(ty*8 + i)*PS_STR + k];
#pragma unroll
                for (int jj = 0; jj < 8; jj++)
                    O[i][jj] = fmaf(pv, vv[jj], O[i][jj]);
            }
        }
    }

    float* outp = g_attn + ((size_t)(b*S_ + iq*128))*H_ + nh*HD_;
#pragma unroll
    for (int i = 0; i < 8; i++) {
        float inv = 1.f / lrow[i];
        int r = ty*8 + i;
#pragma unroll
        for (int jj = 0; jj < 8; jj++)
            outp[(size_t)r*H_ + tx + 16*jj] = O[i][jj] * inv;
    }
}

// ---------------- launch ----------------------------------------------------
extern "C" void kernel_launch(void* const* d_in, const int* in_sizes, int n_in,
                              void* d_out, int out_size)
{
    (void)in_sizes; (void)n_in; (void)out_size;
    const float* X  = (const float*)d_in[0];
    const float* Wq = (const float*)d_in[2];
    const float* bq = (const float*)d_in[3];
    const float* Wk = (const float*)d_in[4];
    const float* bk = (const float*)d_in[5];
    const float* Wv = (const float*)d_in[6];
    const float* bv = (const float*)d_in[7];
    const float* Wo = (const float*)d_in[8];
    const float* bo = (const float*)d_in[9];
    float* out = (float*)d_out;

    rope_table_kernel<<<(S_*64 + 255)/256, 256>>>();
    convert_split_kernel<<<M_*H_/1024, 256>>>(X, 0);
    dim3 tb(32, 8), tg(H_/32, H_/32);
    transpose_split_kernel<<<tg, tb>>>(Wq, 0);
    transpose_split_kernel<<<tg, tb>>>(Wk, 1);
    transpose_split_kernel<<<tg, tb>>>(Wv, 2);
    transpose_split_kernel<<<tg, tb>>>(Wo, 3);

    cudaFuncSetAttribute(gemm_qkv_tc, cudaFuncAttributeMaxDynamicSharedMemorySize,
                         SMEM_GG);
    gemm_qkv_tc<<<dim3(48, 32), 256, SMEM_GG>>>(bq, bk, bv);

    size_t smem = (size_t)(2*128*QS_STR + 128*PS_STR) * sizeof(float);
    cudaFuncSetAttribute(attn_kernel, cudaFuncAttributeMaxDynamicSharedMemorySize,
                         (int)smem);
    attn_kernel<<<dim3(S_/128, B_*NH_), 256, smem>>>();

    convert_split_kernel<<<M_*H_/1024, 256>>>(nullptr, 1);
    cudaFuncSetAttribute(gemm_out_tc, cudaFuncAttributeMaxDynamicSharedMemorySize,
                         SMEM_GG);
    gemm_out_tc<<<dim3(16, 32), 256, SMEM_GG>>>(bo, out);
}

// round 6
// speedup vs baseline: 2.0731x; 1.3751x over previous
#include <cuda_runtime.h>
#include <cuda_bf16.h>
#include <math.h>
#include <stdint.h>

#define B_  2
#define S_  2048
#define H_  2048
#define NH_ 16
#define HD_ 128
#define M_  (B_*S_)   // 4096

// ---------------- scratch (device globals) ---------------------------------
__device__ float g_attn[M_*H_];
__device__ float g_cos[S_*64];
__device__ float g_sin[S_*64];

__device__ __align__(16) __nv_bfloat16 g_Ah[M_*H_],  g_Al[M_*H_];     // A hi/lo
__device__ __align__(16) __nv_bfloat16 g_Bh[3*H_*H_], g_Bl[3*H_*H_];  // W^T qkv
__device__ __align__(16) __nv_bfloat16 g_Wh[H_*H_],  g_Wl[H_*H_];     // Wo^T

// attention operands (bf16 hi/lo splits)
__device__ __align__(16) __nv_bfloat16 g_qh[B_*NH_*S_*HD_], g_ql[B_*NH_*S_*HD_];
__device__ __align__(16) __nv_bfloat16 g_kh[B_*NH_*S_*HD_], g_kl[B_*NH_*S_*HD_];
__device__ __align__(16) __nv_bfloat16 g_vth[B_*NH_*HD_*S_], g_vtl[B_*NH_*HD_*S_];

// ---------------- PTX helpers ----------------------------------------------
__device__ __forceinline__ uint32_t smem_u32(const void* p) {
    uint32_t a;
    asm("{ .reg .u64 t; cvta.to.shared.u64 t, %1; cvt.u32.u64 %0, t; }"
        : "=r"(a) : "l"(p));
    return a;
}
#define CP16(dst, src) \
    asm volatile("cp.async.cg.shared.global [%0], [%1], 16;" \
                 :: "r"(dst), "l"(src) : "memory")
#define CP_COMMIT() asm volatile("cp.async.commit_group;" ::: "memory")

#define LDM4(r, addr) \
    asm volatile("ldmatrix.sync.aligned.m8n8.x4.shared.b16 {%0,%1,%2,%3}, [%4];" \
        : "=r"((r)[0]), "=r"((r)[1]), "=r"((r)[2]), "=r"((r)[3]) : "r"(addr))

__device__ __forceinline__ void mma_bf16(float* d, const uint32_t* a,
                                         const uint32_t* b) {
    asm volatile("mma.sync.aligned.m16n8k16.row.col.f32.bf16.bf16.f32 "
        "{%0,%1,%2,%3}, {%4,%5,%6,%7}, {%8,%9}, {%0,%1,%2,%3};"
        : "+f"(d[0]), "+f"(d[1]), "+f"(d[2]), "+f"(d[3])
        : "r"(a[0]), "r"(a[1]), "r"(a[2]), "r"(a[3]), "r"(b[0]), "r"(b[1]));
}
__device__ __forceinline__ void mma2(float* d, const uint32_t* a,
                                     uint32_t b0, uint32_t b1) {
    asm volatile("mma.sync.aligned.m16n8k16.row.col.f32.bf16.bf16.f32 "
        "{%0,%1,%2,%3}, {%4,%5,%6,%7}, {%8,%9}, {%0,%1,%2,%3};"
        : "+f"(d[0]), "+f"(d[1]), "+f"(d[2]), "+f"(d[3])
        : "r"(a[0]), "r"(a[1]), "r"(a[2]), "r"(a[3]), "r"(b0), "r"(b1));
}
__device__ __forceinline__ uint32_t packbf(float x, float y) {
    __nv_bfloat162 t = __floats2bfloat162_rn(x, y);
    return *(uint32_t*)&t;
}
__device__ __forceinline__ float rlo(float x) {
    return x - __bfloat162float(__float2bfloat16_rn(x));
}

// ---------------- prep kernels ---------------------------------------------
__global__ void rope_table_kernel()
{
    int idx = blockIdx.x * blockDim.x + threadIdx.x;
    if (idx >= S_ * 64) return;
    int s = idx >> 6, p = idx & 63;
    double invf = exp(-log(10000.0) * (double)p / 64.0);
    double ang  = (double)s * invf;
    g_cos[idx] = (float)cos(ang);
    g_sin[idx] = (float)sin(ang);
}

__global__ void convert_split_kernel(const float* __restrict__ in, int src_sel)
{
    const float* src = src_sel ? g_attn : in;
    int i = (blockIdx.x * blockDim.x + threadIdx.x) * 4;
    float4 v = *(const float4*)&src[i];
    float x[4] = {v.x, v.y, v.z, v.w};
    unsigned short hs[4], ls[4];
#pragma unroll
    for (int j = 0; j < 4; j++) {
        __nv_bfloat16 h = __float2bfloat16(x[j]);
        __nv_bfloat16 l = __float2bfloat16(x[j] - __bfloat162float(h));
        hs[j] = __bfloat16_as_ushort(h); ls[j] = __bfloat16_as_ushort(l);
    }
    *(ushort4*)((unsigned short*)g_Ah + i) = make_ushort4(hs[0], hs[1], hs[2], hs[3]);
    *(ushort4*)((unsigned short*)g_Al + i) = make_ushort4(ls[0], ls[1], ls[2], ls[3]);
}

__global__ void transpose_split_kernel(const float* __restrict__ in, int which)
{
    __nv_bfloat16* hi = (which < 3) ? g_Bh + (size_t)which*H_*H_ : g_Wh;
    __nv_bfloat16* lo = (which < 3) ? g_Bl + (size_t)which*H_*H_ : g_Wl;
    __shared__ float t[32][33];
    int tx = threadIdx.x, ty = threadIdx.y;
    int c0 = blockIdx.x * 32, r0 = blockIdx.y * 32;
#pragma unroll
    for (int k = 0; k < 4; k++)
        t[ty + 8*k][tx] = in[(size_t)(r0 + ty + 8*k) * H_ + c0 + tx];
    __syncthreads();
#pragma unroll
    for (int k = 0; k < 4; k++) {
        float x = t[tx][ty + 8*k];
        __nv_bfloat16 h = __float2bfloat16(x);
        __nv_bfloat16 l = __float2bfloat16(x - __bfloat162float(h));
        size_t o = (size_t)(c0 + ty + 8*k) * H_ + r0 + tx;
        hi[o] = h; lo[o] = l;
    }
}

// ---------------- HMMA GEMM mainloop (unchanged core) -----------------------
#define RSTR   80
#define REG_B  (128*RSTR)
#define STG_B  (4*REG_B)
#define SMEM_GG (4*STG_B)

__device__ __forceinline__ void ld_region(uint32_t dst,
    const __nv_bfloat16* __restrict__ src, int row0, int kb, int tid)
{
#pragma unroll
    for (int it = 0; it < 2; it++) {
        int idx = tid + it*256;
        int r = idx >> 2, c = idx & 3;
        CP16(dst + r*RSTR + c*16,
             (const void*)(src + (size_t)(row0 + r) * H_ + kb + c*8));
    }
}
__device__ __forceinline__ void ld_stage(uint32_t s0,
    const __nv_bfloat16* Ah, const __nv_bfloat16* Al,
    const __nv_bfloat16* Bh, const __nv_bfloat16* Bl,
    int m0, int n0, int kb, int tid)
{
    ld_region(s0,           Ah, m0, kb, tid);
    ld_region(s0 +   REG_B, Al, m0, kb, tid);
    ld_region(s0 + 2*REG_B, Bh, n0, kb, tid);
    ld_region(s0 + 3*REG_B, Bl, n0, kb, tid);
    CP_COMMIT();
}

__device__ __forceinline__ void hmma_mainloop(
    const __nv_bfloat16* Ah, const __nv_bfloat16* Al,
    const __nv_bfloat16* Bh, const __nv_bfloat16* Bl,
    int m0, int n0, uint32_t sb, float acc[2][8][4])
{
    const int tid = threadIdx.x, lane = tid & 31, w = tid >> 5;
#pragma unroll
    for (int i = 0; i < 2; i++)
#pragma unroll
        for (int j = 0; j < 8; j++)
#pragma unroll
            for (int k = 0; k < 4; k++) acc[i][j][k] = 0.f;

    ld_stage(sb,           Ah, Al, Bh, Bl, m0, n0, 0,  tid);
    ld_stage(sb +   STG_B, Ah, Al, Bh, Bl, m0, n0, 32, tid);
    ld_stage(sb + 2*STG_B, Ah, Al, Bh, Bl, m0, n0, 64, tid);

    const int arow = (w >> 1)*32 + (lane & 15);
    const int brow = (w & 1)*32 + (lane & 15);
    const int fcol = (lane >> 4) << 4;

    for (int ch = 0; ch < 64; ch++) {
        if (ch < 62)       asm volatile("cp.async.wait_group 2;" ::: "memory");
        else if (ch == 62) asm volatile("cp.async.wait_group 1;" ::: "memory");
        else               asm volatile("cp.async.wait_group 0;" ::: "memory");
        __syncthreads();
        uint32_t s0 = sb + (ch & 3)*STG_B;
#pragma unroll
        for (int kk = 0; kk < 2; kk++) {
            int kB = kk*32 + fcol;
            uint32_t a[2][2][4], b[2][8][2];
#pragma unroll
            for (int t = 0; t < 2; t++)
#pragma unroll
                for (int mi = 0; mi < 2; mi++)
                    LDM4(a[t][mi], s0 + t*REG_B + (arow + mi*16)*RSTR + kB);
#pragma unroll
            for (int t = 0; t < 2; t++)
#pragma unroll
                for (int p = 0; p < 4; p++) {
                    int r = brow + (p & 1)*16 + ((p & 2) ? 64 : 0);
                    uint32_t q[4];
                    LDM4(q, s0 + (2 + t)*REG_B + r*RSTR + kB);
                    b[t][2*p][0]   = q[0]; b[t][2*p][1]   = q[2];
                    b[t][2*p+1][0] = q[1]; b[t][2*p+1][1] = q[3];
                }
#pragma unroll
            for (int mi = 0; mi < 2; mi++)
#pragma unroll
                for (int nj = 0; nj < 8; nj++)
                    mma_bf16(acc[mi][nj], a[0][mi], b[0][nj]);
#pragma unroll
            for (int mi = 0; mi < 2; mi++)
#pragma unroll
                for (int nj = 0; nj < 8; nj++)
                    mma_bf16(acc[mi][nj], a[0][mi], b[1][nj]);
#pragma unroll
            for (int mi = 0; mi < 2; mi++)
#pragma unroll
                for (int nj = 0; nj < 8; nj++)
                    mma_bf16(acc[mi][nj], a[1][mi], b[0][nj]);
        }
        if (ch + 3 < 64)
            ld_stage(sb + ((ch + 3) & 3)*STG_B, Ah, Al, Bh, Bl,
                     m0, n0, (ch + 3)*32, tid);
    }
}

// ---------------- QKV projection + bias + RoPE -> bf16 splits ---------------
__global__ __launch_bounds__(256, 1)
void gemm_qkv_tc(const float* __restrict__ bq, const float* __restrict__ bk,
                 const float* __restrict__ bv)
{
    extern __shared__ char dsm[];
    uint32_t sb = smem_u32(dsm);
    const int tid = threadIdx.x, lane = tid & 31, w = tid >> 5;
    const int z = blockIdx.x >> 4, nh = blockIdx.x & 15;
    const int m0 = blockIdx.y * 128, n0 = nh * 128;
    const float* bias = (z == 0) ? bq : (z == 1) ? bk : bv;
    const __nv_bfloat16* Bh = g_Bh + (size_t)z * H_ * H_;
    const __nv_bfloat16* Bl = g_Bl + (size_t)z * H_ * H_;

    float acc[2][8][4];
    hmma_mainloop(g_Ah, g_Al, Bh, Bl, m0, n0, sb, acc);

    const int gr = lane >> 2, gc = (lane & 3)*2;
    __nv_bfloat16* oh = (z == 0) ? g_qh : g_kh;
    __nv_bfloat16* ol = (z == 0) ? g_ql : g_kl;
#pragma unroll
    for (int mi = 0; mi < 2; mi++)
#pragma unroll
        for (int h = 0; h < 2; h++) {
            int m = m0 + (w >> 1)*32 + mi*16 + gr + h*8;
            int bb = m >> 11, s = m & 2047;
#pragma unroll
            for (int nj = 0; nj < 4; nj++) {
                int c = (w & 1)*32 + nj*8 + gc;
                float vl0 = acc[mi][nj][h*2+0]   + bias[n0 + c];
                float vl1 = acc[mi][nj][h*2+1]   + bias[n0 + c + 1];
                float vh0 = acc[mi][nj+4][h*2+0] + bias[n0 + 64 + c];
                float vh1 = acc[mi][nj+4][h*2+1] + bias[n0 + 64 + c + 1];
                if (z < 2) {
                    float cs0 = g_cos[s*64 + c],     sn0 = g_sin[s*64 + c];
                    float cs1 = g_cos[s*64 + c + 1], sn1 = g_sin[s*64 + c + 1];
                    float o0 = vl0*cs0 - vh0*sn0, o2 = vh0*cs0 + vl0*sn0;
                    float o1 = vl1*cs1 - vh1*sn1, o3 = vh1*cs1 + vl1*sn1;
                    size_t base = ((size_t)(bb*NH_ + nh)*S_ + s) * HD_;
                    *(uint32_t*)&oh[base + c]      = packbf(o0, o1);
                    *(uint32_t*)&ol[base + c]      = packbf(rlo(o0), rlo(o1));
                    *(uint32_t*)&oh[base + 64 + c] = packbf(o2, o3);
                    *(uint32_t*)&ol[base + 64 + c] = packbf(rlo(o2), rlo(o3));
                } else {
                    size_t vb = (size_t)(bb*NH_ + nh) * HD_;
                    float vv[4] = {vl0, vl1, vh0, vh1};
                    int   cc[4] = {c, c + 1, 64 + c, 64 + c + 1};
#pragma unroll
                    for (int u = 0; u < 4; u++) {
                        g_vth[(vb + cc[u])*S_ + s] = __float2bfloat16_rn(vv[u]);
                        g_vtl[(vb + cc[u])*S_ + s] = __float2bfloat16_rn(rlo(vv[u]));
                    }
                }
            }
        }
}

// ---------------- output projection + bias ----------------------------------
__global__ __launch_bounds__(256, 1)
void gemm_out_tc(const float* __restrict__ bo, float* __restrict__ out)
{
    extern __shared__ char dsm[];
    uint32_t sb = smem_u32(dsm);
    const int tid = threadIdx.x, lane = tid & 31, w = tid >> 5;
    const int m0 = blockIdx.y * 128, n0 = blockIdx.x * 128;

    float acc[2][8][4];
    hmma_mainloop(g_Ah, g_Al, g_Wh, g_Wl, m0, n0, sb, acc);

    const int gr = lane >> 2, gc = (lane & 3)*2;
#pragma unroll
    for (int mi = 0; mi < 2; mi++)
#pragma unroll
        for (int h = 0; h < 2; h++) {
            int m = m0 + (w >> 1)*32 + mi*16 + gr + h*8;
            float* op = out + (size_t)m * H_ + n0;
#pragma unroll
            for (int nj = 0; nj < 4; nj++) {
                int c = (w & 1)*32 + nj*8 + gc;
                *(float2*)&op[c] = make_float2(
                    acc[mi][nj][h*2+0] + bo[n0 + c],
                    acc[mi][nj][h*2+1] + bo[n0 + c + 1]);
                *(float2*)&op[64 + c] = make_float2(
                    acc[mi][nj+4][h*2+0] + bo[n0 + 64 + c],
                    acc[mi][nj+4][h*2+1] + bo[n0 + 64 + c + 1]);
            }
        }
}

// ---------------- tensor-core causal flash attention ------------------------
// BQ=128/CTA, 8 warps x 16 rows. kv tiles 128. bf16 3-term splits everywhere.
// smem regions (stride 272B, 128 rows): Qh Ql Kh Kl Vh Vl
#define ASTR 272
#define ARGN (128*ASTR)          // 34816
#define SMEM_AT (6*ARGN)         // 208896

__device__ __forceinline__ void attn_ld(uint32_t dst,
    const __nv_bfloat16* __restrict__ src, int stride, int tid)
{
#pragma unroll
    for (int it = 0; it < 8; it++) {
        int idx = tid + it*256;            // 2048 = 128 rows x 16 chunks
        int r = idx >> 4, c = idx & 15;
        CP16(dst + r*ASTR + c*16, (const void*)(src + (size_t)r*stride + c*8));
    }
}

__global__ __launch_bounds__(256, 1)
void attn_tc_kernel()
{
    extern __shared__ char dsm[];
    uint32_t sb = smem_u32(dsm);
    const int tid = threadIdx.x, lane = tid & 31, wm = tid >> 5;
    const int gr = lane >> 2, gc = (lane & 3)*2;
    const int bh = blockIdx.y;
    const int iq = (int)gridDim.x - 1 - (int)blockIdx.x;
    const int laneoff = (lane & 15)*ASTR + (lane >> 4)*16;
    const float scale = 0.08838834764831845f;

    const size_t qkbase = (size_t)bh * S_ * HD_;
    const __nv_bfloat16* Qh = g_qh + qkbase + (size_t)iq*128*HD_;
    const __nv_bfloat16* Ql = g_ql + qkbase + (size_t)iq*128*HD_;
    const size_t vbase = (size_t)bh * HD_ * S_;

    // prefetch: G0 = Q, G1 = K(0), G2 = V(0)
    attn_ld(sb + 0*ARGN, Qh, HD_, tid);
    attn_ld(sb + 1*ARGN, Ql, HD_, tid);
    CP_COMMIT();
    attn_ld(sb + 2*ARGN, g_kh + qkbase, HD_, tid);
    attn_ld(sb + 3*ARGN, g_kl + qkbase, HD_, tid);
    CP_COMMIT();
    attn_ld(sb + 4*ARGN, g_vth + vbase, S_, tid);
    attn_ld(sb + 5*ARGN, g_vtl + vbase, S_, tid);
    CP_COMMIT();

    const uint32_t qhb = sb + 0*ARGN + wm*16*ASTR + laneoff;
    const uint32_t qlb = sb + 1*ARGN + wm*16*ASTR + laneoff;
    const uint32_t khb = sb + 2*ARGN + laneoff;
    const uint32_t klb = sb + 3*ARGN + laneoff;
    const uint32_t vhb = sb + 4*ARGN + laneoff;
    const uint32_t vlb = sb + 5*ARGN + laneoff;

    float O[16][4];
#pragma unroll
    for (int j = 0; j < 16; j++)
#pragma unroll
        for (int k = 0; k < 4; k++) O[j][k] = 0.f;
    float m0r = -1e30f, m1r = -1e30f, l0r = 0.f, l1r = 0.f;

    for (int jt = 0; jt <= iq; jt++) {
        asm volatile("cp.async.wait_group 1;" ::: "memory");
        __syncthreads();                               // Q + K(jt) ready

        // ---- S = Qh*Kh + Qh*Kl + Ql*Kh ----
        float Sf[16][4];
#pragma unroll
        for (int j = 0; j < 16; j++)
#pragma unroll
            for (int k = 0; k < 4; k++) Sf[j][k] = 0.f;
#pragma unroll
        for (int t = 0; t < 8; t++) {
            uint32_t ah[4], al[4];
            LDM4(ah, qhb + t*32);
            LDM4(al, qlb + t*32);
#pragma unroll
            for (int jp = 0; jp < 8; jp++) {
                uint32_t bh4[4], bl4[4];
                LDM4(bh4, khb + jp*16*ASTR + t*32);
                LDM4(bl4, klb + jp*16*ASTR + t*32);
                mma2(Sf[2*jp],   ah, bh4[0], bh4[2]);
                mma2(Sf[2*jp+1], ah, bh4[1], bh4[3]);
                mma2(Sf[2*jp],   ah, bl4[0], bl4[2]);
                mma2(Sf[2*jp+1], ah, bl4[1], bl4[3]);
                mma2(Sf[2*jp],   al, bh4[0], bh4[2]);
                mma2(Sf[2*jp+1], al, bh4[1], bh4[3]);
            }
        }
        __syncthreads();                               // all warps done with K
        if (jt < iq) {                                 // prefetch K(jt+1)
            attn_ld(sb + 2*ARGN, g_kh + qkbase + (size_t)(jt+1)*128*HD_, HD_, tid);
            attn_ld(sb + 3*ARGN, g_kl + qkbase + (size_t)(jt+1)*128*HD_, HD_, tid);
            CP_COMMIT();
        }

        // ---- scale + causal mask ----
        const int r0 = wm*16 + gr, r1 = r0 + 8;
        if (jt == iq) {
#pragma unroll
            for (int j = 0; j < 16; j++) {
                int cA = j*8 + gc, cB = cA + 1;
                Sf[j][0] = (cA > r0) ? -1e30f : Sf[j][0]*scale;
                Sf[j][1] = (cB > r0) ? -1e30f : Sf[j][1]*scale;
                Sf[j][2] = (cA > r1) ? -1e30f : Sf[j][2]*scale;
                Sf[j][3] = (cB > r1) ? -1e30f : Sf[j][3]*scale;
            }
        } else {
#pragma unroll
            for (int j = 0; j < 16; j++)
#pragma unroll
                for (int k = 0; k < 4; k++) Sf[j][k] *= scale;
        }

        // ---- online softmax ----
        float mx0 = -1e30f, mx1 = -1e30f;
#pragma unroll
        for (int j = 0; j < 16; j++) {
            mx0 = fmaxf(mx0, fmaxf(Sf[j][0], Sf[j][1]));
            mx1 = fmaxf(mx1, fmaxf(Sf[j][2], Sf[j][3]));
        }
        mx0 = fmaxf(mx0, __shfl_xor_sync(0xffffffffu, mx0, 1));
        mx0 = fmaxf(mx0, __shfl_xor_sync(0xffffffffu, mx0, 2));
        mx1 = fmaxf(mx1, __shfl_xor_sync(0xffffffffu, mx1, 1));
        mx1 = fmaxf(mx1, __shfl_xor_sync(0xffffffffu, mx1, 2));
        float mn0 = fmaxf(m0r, mx0), mn1 = fmaxf(m1r, mx1);
        float al0 = __expf(m0r - mn0), al1 = __expf(m1r - mn1);
        m0r = mn0; m1r = mn1;
        float sum0 = 0.f, sum1 = 0.f;
#pragma unroll
        for (int j = 0; j < 16; j++) {
            Sf[j][0] = __expf(Sf[j][0] - mn0); sum0 += Sf[j][0];
            Sf[j][1] = __expf(Sf[j][1] - mn0); sum0 += Sf[j][1];
            Sf[j][2] = __expf(Sf[j][2] - mn1); sum1 += Sf[j][2];
            Sf[j][3] = __expf(Sf[j][3] - mn1); sum1 += Sf[j][3];
        }
        sum0 += __shfl_xor_sync(0xffffffffu, sum0, 1);
        sum0 += __shfl_xor_sync(0xffffffffu, sum0, 2);
        sum1 += __shfl_xor_sync(0xffffffffu, sum1, 1);
        sum1 += __shfl_xor_sync(0xffffffffu, sum1, 2);
        l0r = l0r*al0 + sum0; l1r = l1r*al1 + sum1;
#pragma unroll
        for (int j = 0; j < 16; j++) {
            O[j][0] *= al0; O[j][1] *= al0;
            O[j][2] *= al1; O[j][3] *= al1;
        }

        asm volatile("cp.async.wait_group 1;" ::: "memory");
        __syncthreads();                               // V(jt) ready

        // ---- O += Ph*Vh + Pl*Vh + Ph*Vl ----
#pragma unroll
        for (int t = 0; t < 8; t++) {
            uint32_t aPh[4], aPl[4];
            aPh[0] = packbf(Sf[2*t][0],   Sf[2*t][1]);
            aPh[1] = packbf(Sf[2*t][2],   Sf[2*t][3]);
            aPh[2] = packbf(Sf[2*t+1][0], Sf[2*t+1][1]);
            aPh[3] = packbf(Sf[2*t+1][2], Sf[2*t+1][3]);
            aPl[0] = packbf(rlo(Sf[2*t][0]),   rlo(Sf[2*t][1]));
            aPl[1] = packbf(rlo(Sf[2*t][2]),   rlo(Sf[2*t][3]));
            aPl[2] = packbf(rlo(Sf[2*t+1][0]), rlo(Sf[2*t+1][1]));
            aPl[3] = packbf(rlo(Sf[2*t+1][2]), rlo(Sf[2*t+1][3]));
#pragma unroll
            for (int jp = 0; jp < 8; jp++) {
                uint32_t bh4[4], bl4[4];
                LDM4(bh4, vhb + jp*16*ASTR + t*32);
                LDM4(bl4, vlb + jp*16*ASTR + t*32);
                mma2(O[2*jp],   aPh, bh4[0], bh4[2]);
                mma2(O[2*jp+1], aPh, bh4[1], bh4[3]);
                mma2(O[2*jp],   aPl, bh4[0], bh4[2]);
                mma2(O[2*jp+1], aPl, bh4[1], bh4[3]);
                mma2(O[2*jp],   aPh, bl4[0], bl4[2]);
                mma2(O[2*jp+1], aPh, bl4[1], bl4[3]);
            }
        }
        __syncthreads();                               // done reading V
        if (jt < iq) {                                 // prefetch V(jt+1)
            attn_ld(sb + 4*ARGN, g_vth + vbase + (size_t)(jt+1)*128, S_, tid);
            attn_ld(sb + 5*ARGN, g_vtl + vbase + (size_t)(jt+1)*128, S_, tid);
            CP_COMMIT();
        }
    }

    // ---- finalize ----
    const int b = bh >> 4, nh = bh & 15;
    float inv0 = 1.f / l0r, inv1 = 1.f / l1r;
    size_t row0 = (size_t)(b*S_ + iq*128 + wm*16 + gr);
#pragma unroll
    for (int j = 0; j < 16; j++) {
        int col = nh*HD_ + j*8 + gc;
        *(float2*)&g_attn[row0*H_ + col] =
            make_float2(O[j][0]*inv0, O[j][1]*inv0);
        *(float2*)&g_attn[(row0 + 8)*H_ + col] =
            make_float2(O[j][2]*inv1, O[j][3]*inv1);
    }
}

// ---------------- launch ----------------------------------------------------
extern "C" void kernel_launch(void* const* d_in, const int* in_sizes, int n_in,
                              void* d_out, int out_size)
{
    (void)in_sizes; (void)n_in; (void)out_size;
    const float* X  = (const float*)d_in[0];
    const float* Wq = (const float*)d_in[2];
    const float* bq = (const float*)d_in[3];
    const float* Wk = (const float*)d_in[4];
    const float* bk = (const float*)d_in[5];
    const float* Wv = (const float*)d_in[6];
    const float* bv = (const float*)d_in[7];
    const float* Wo = (const float*)d_in[8];
    const float* bo = (const float*)d_in[9];
    float* out = (float*)d_out;

    rope_table_kernel<<<(S_*64 + 255)/256, 256>>>();
    convert_split_kernel<<<M_*H_/1024, 256>>>(X, 0);
    dim3 tb(32, 8), tg(H_/32, H_/32);
    transpose_split_kernel<<<tg, tb>>>(Wq, 0);
    transpose_split_kernel<<<tg, tb>>>(Wk, 1);
    transpose_split_kernel<<<tg, tb>>>(Wv, 2);
    transpose_split_kernel<<<tg, tb>>>(Wo, 3);

    cudaFuncSetAttribute(gemm_qkv_tc, cudaFuncAttributeMaxDynamicSharedMemorySize,
                         SMEM_GG);
    gemm_qkv_tc<<<dim3(48, 32), 256, SMEM_GG>>>(bq, bk, bv);

    cudaFuncSetAttribute(attn_tc_kernel, cudaFuncAttributeMaxDynamicSharedMemorySize,
                         SMEM_AT);
    attn_tc_kernel<<<dim3(S_/128, B_*NH_), 256, SMEM_AT>>>();

    convert_split_kernel<<<M_*H_/1024, 256>>>(nullptr, 1);
    cudaFuncSetAttribute(gemm_out_tc, cudaFuncAttributeMaxDynamicSharedMemorySize,
                         SMEM_GG);
    gemm_out_tc<<<dim3(16, 32), 256, SMEM_GG>>>(bo, out);
}

// round 7
// speedup vs baseline: 2.7206x; 1.3123x over previous
#include <cuda_runtime.h>
#include <cuda_bf16.h>
#include <cuda_fp16.h>
#include <math.h>
#include <stdint.h>

#define B_  2
#define S_  2048
#define H_  2048
#define NH_ 16
#define HD_ 128
#define M_  (B_*S_)   // 4096

// ---------------- scratch (device globals) ---------------------------------
__device__ float g_attn[M_*H_];
__device__ float g_cos[S_*64];
__device__ float g_sin[S_*64];

__device__ __align__(16) __nv_bfloat16 g_Ah[M_*H_],  g_Al[M_*H_];     // A hi/lo bf16
__device__ __align__(16) __half        g_Af[M_*H_];                   // A fp16
__device__ __align__(16) __nv_bfloat16 g_Bh[2*H_*H_], g_Bl[2*H_*H_];  // Wq/Wk^T bf16
__device__ __align__(16) __half        g_Bf[H_*H_];                   // Wv^T fp16
__device__ __align__(16) __half        g_Wf[H_*H_];                   // Wo^T fp16

// attention operands (bf16 hi/lo splits)
__device__ __align__(16) __nv_bfloat16 g_qh[B_*NH_*S_*HD_], g_ql[B_*NH_*S_*HD_];
__device__ __align__(16) __nv_bfloat16 g_kh[B_*NH_*S_*HD_], g_kl[B_*NH_*S_*HD_];
__device__ __align__(16) __nv_bfloat16 g_vth[B_*NH_*HD_*S_], g_vtl[B_*NH_*HD_*S_];

// ---------------- PTX helpers ----------------------------------------------
__device__ __forceinline__ uint32_t smem_u32(const void* p) {
    uint32_t a;
    asm("{ .reg .u64 t; cvta.to.shared.u64 t, %1; cvt.u32.u64 %0, t; }"
        : "=r"(a) : "l"(p));
    return a;
}
#define CP16(dst, src) \
    asm volatile("cp.async.cg.shared.global [%0], [%1], 16;" \
                 :: "r"(dst), "l"(src) : "memory")
#define CP_COMMIT() asm volatile("cp.async.commit_group;" ::: "memory")

#define LDM4(r, addr) \
    asm volatile("ldmatrix.sync.aligned.m8n8.x4.shared.b16 {%0,%1,%2,%3}, [%4];" \
        : "=r"((r)[0]), "=r"((r)[1]), "=r"((r)[2]), "=r"((r)[3]) : "r"(addr))

__device__ __forceinline__ void mma_bf16(float* d, const uint32_t* a,
                                         const uint32_t* b) {
    asm volatile("mma.sync.aligned.m16n8k16.row.col.f32.bf16.bf16.f32 "
        "{%0,%1,%2,%3}, {%4,%5,%6,%7}, {%8,%9}, {%0,%1,%2,%3};"
        : "+f"(d[0]), "+f"(d[1]), "+f"(d[2]), "+f"(d[3])
        : "r"(a[0]), "r"(a[1]), "r"(a[2]), "r"(a[3]), "r"(b[0]), "r"(b[1]));
}
__device__ __forceinline__ void mma_f16(float* d, const uint32_t* a,
                                        uint32_t b0, uint32_t b1) {
    asm volatile("mma.sync.aligned.m16n8k16.row.col.f32.f16.f16.f32 "
        "{%0,%1,%2,%3}, {%4,%5,%6,%7}, {%8,%9}, {%0,%1,%2,%3};"
        : "+f"(d[0]), "+f"(d[1]), "+f"(d[2]), "+f"(d[3])
        : "r"(a[0]), "r"(a[1]), "r"(a[2]), "r"(a[3]), "r"(b0), "r"(b1));
}
__device__ __forceinline__ void mma2(float* d, const uint32_t* a,
                                     uint32_t b0, uint32_t b1) {
    asm volatile("mma.sync.aligned.m16n8k16.row.col.f32.bf16.bf16.f32 "
        "{%0,%1,%2,%3}, {%4,%5,%6,%7}, {%8,%9}, {%0,%1,%2,%3};"
        : "+f"(d[0]), "+f"(d[1]), "+f"(d[2]), "+f"(d[3])
        : "r"(a[0]), "r"(a[1]), "r"(a[2]), "r"(a[3]), "r"(b0), "r"(b1));
}
__device__ __forceinline__ uint32_t packbf(float x, float y) {
    __nv_bfloat162 t = __floats2bfloat162_rn(x, y);
    return *(uint32_t*)&t;
}
__device__ __forceinline__ float rlo(float x) {
    return x - __bfloat162float(__float2bfloat16_rn(x));
}

// ---------------- prep kernels ---------------------------------------------
__global__ void rope_table_kernel()
{
    int idx = blockIdx.x * blockDim.x + threadIdx.x;
    if (idx >= S_ * 64) return;
    int s = idx >> 6, p = idx & 63;
    double invf = exp(-log(10000.0) * (double)p / 64.0);
    double ang  = (double)s * invf;
    g_cos[idx] = (float)cos(ang);
    g_sin[idx] = (float)sin(ang);
}

// writes bf16 hi/lo (g_Ah/g_Al) and fp16 (g_Af)
__global__ void convert_split_kernel(const float* __restrict__ in, int src_sel)
{
    const float* src = src_sel ? g_attn : in;
    int i = (blockIdx.x * blockDim.x + threadIdx.x) * 4;
    float4 v = *(const float4*)&src[i];
    float x[4] = {v.x, v.y, v.z, v.w};
    unsigned short hs[4], ls[4], fs[4];
#pragma unroll
    for (int j = 0; j < 4; j++) {
        __nv_bfloat16 h = __float2bfloat16(x[j]);
        __nv_bfloat16 l = __float2bfloat16(x[j] - __bfloat162float(h));
        __half f = __float2half_rn(x[j]);
        hs[j] = __bfloat16_as_ushort(h); ls[j] = __bfloat16_as_ushort(l);
        fs[j] = __half_as_ushort(f);
    }
    *(ushort4*)((unsigned short*)g_Ah + i) = make_ushort4(hs[0], hs[1], hs[2], hs[3]);
    *(ushort4*)((unsigned short*)g_Al + i) = make_ushort4(ls[0], ls[1], ls[2], ls[3]);
    *(ushort4*)((unsigned short*)g_Af + i) = make_ushort4(fs[0], fs[1], fs[2], fs[3]);
}

// which: 0,1 -> bf16 hi/lo slabs (Wq,Wk); 2 -> g_Bf fp16 (Wv); 3 -> g_Wf fp16 (Wo)
__global__ void transpose_split_kernel(const float* __restrict__ in, int which)
{
    __shared__ float t[32][33];
    int tx = threadIdx.x, ty = threadIdx.y;
    int c0 = blockIdx.x * 32, r0 = blockIdx.y * 32;
#pragma unroll
    for (int k = 0; k < 4; k++)
        t[ty + 8*k][tx] = in[(size_t)(r0 + ty + 8*k) * H_ + c0 + tx];
    __syncthreads();
    if (which < 2) {
        __nv_bfloat16* hi = g_Bh + (size_t)which*H_*H_;
        __nv_bfloat16* lo = g_Bl + (size_t)which*H_*H_;
#pragma unroll
        for (int k = 0; k < 4; k++) {
            float x = t[tx][ty + 8*k];
            __nv_bfloat16 h = __float2bfloat16(x);
            __nv_bfloat16 l = __float2bfloat16(x - __bfloat162float(h));
            size_t o = (size_t)(c0 + ty + 8*k) * H_ + r0 + tx;
            hi[o] = h; lo[o] = l;
        }
    } else {
        __half* dst = (which == 2) ? g_Bf : g_Wf;
#pragma unroll
        for (int k = 0; k < 4; k++) {
            float x = t[tx][ty + 8*k];
            size_t o = (size_t)(c0 + ty + 8*k) * H_ + r0 + tx;
            dst[o] = __float2half_rn(x);
        }
    }
}

// ---------------- shared GEMM loader ----------------------------------------
#define RSTR   80
#define REG_B  (128*RSTR)        // 10240
#define STG_B  (4*REG_B)         // bf16 3-term stage: Ah|Al|Bh|Bl
#define SMEM_GG (4*STG_B)        // 163840
#define FSTG_B (2*REG_B)         // fp16 stage: A|B
#define SMEM_GF (4*FSTG_B)       // 81920

__device__ __forceinline__ void ld_region(uint32_t dst,
    const __nv_bfloat16* __restrict__ src, int row0, int kb, int tid)
{
#pragma unroll
    for (int it = 0; it < 2; it++) {
        int idx = tid + it*256;
        int r = idx >> 2, c = idx & 3;
        CP16(dst + r*RSTR + c*16,
             (const void*)(src + (size_t)(row0 + r) * H_ + kb + c*8));
    }
}
__device__ __forceinline__ void ld_stage(uint32_t s0,
    const __nv_bfloat16* Ah, const __nv_bfloat16* Al,
    const __nv_bfloat16* Bh, const __nv_bfloat16* Bl,
    int m0, int n0, int kb, int tid)
{
    ld_region(s0,           Ah, m0, kb, tid);
    ld_region(s0 +   REG_B, Al, m0, kb, tid);
    ld_region(s0 + 2*REG_B, Bh, n0, kb, tid);
    ld_region(s0 + 3*REG_B, Bl, n0, kb, tid);
    CP_COMMIT();
}
__device__ __forceinline__ void ld_stage_f16(uint32_t s0,
    const __half* A, const __half* Bm, int m0, int n0, int kb, int tid)
{
    ld_region(s0,         (const __nv_bfloat16*)A,  m0, kb, tid);
    ld_region(s0 + REG_B, (const __nv_bfloat16*)Bm, n0, kb, tid);
    CP_COMMIT();
}

// ---------------- 3-term bf16 mainloop --------------------------------------
__device__ __forceinline__ void hmma_mainloop(
    const __nv_bfloat16* Ah, const __nv_bfloat16* Al,
    const __nv_bfloat16* Bh, const __nv_bfloat16* Bl,
    int m0, int n0, uint32_t sb, float acc[2][8][4])
{
    const int tid = threadIdx.x, lane = tid & 31, w = tid >> 5;
#pragma unroll
    for (int i = 0; i < 2; i++)
#pragma unroll
        for (int j = 0; j < 8; j++)
#pragma unroll
            for (int k = 0; k < 4; k++) acc[i][j][k] = 0.f;

    ld_stage(sb,           Ah, Al, Bh, Bl, m0, n0, 0,  tid);
    ld_stage(sb +   STG_B, Ah, Al, Bh, Bl, m0, n0, 32, tid);
    ld_stage(sb + 2*STG_B, Ah, Al, Bh, Bl, m0, n0, 64, tid);

    const int arow = (w >> 1)*32 + (lane & 15);
    const int brow = (w & 1)*32 + (lane & 15);
    const int fcol = (lane >> 4) << 4;

    for (int ch = 0; ch < 64; ch++) {
        if (ch < 62)       asm volatile("cp.async.wait_group 2;" ::: "memory");
        else if (ch == 62) asm volatile("cp.async.wait_group 1;" ::: "memory");
        else               asm volatile("cp.async.wait_group 0;" ::: "memory");
        __syncthreads();
        uint32_t s0 = sb + (ch & 3)*STG_B;
#pragma unroll
        for (int kk = 0; kk < 2; kk++) {
            int kB = kk*32 + fcol;
            uint32_t a[2][2][4], b[2][8][2];
#pragma unroll
            for (int t = 0; t < 2; t++)
#pragma unroll
                for (int mi = 0; mi < 2; mi++)
                    LDM4(a[t][mi], s0 + t*REG_B + (arow + mi*16)*RSTR + kB);
#pragma unroll
            for (int t = 0; t < 2; t++)
#pragma unroll
                for (int p = 0; p < 4; p++) {
                    int r = brow + (p & 1)*16 + ((p & 2) ? 64 : 0);
                    uint32_t q[4];
                    LDM4(q, s0 + (2 + t)*REG_B + r*RSTR + kB);
                    b[t][2*p][0]   = q[0]; b[t][2*p][1]   = q[2];
                    b[t][2*p+1][0] = q[1]; b[t][2*p+1][1] = q[3];
                }
#pragma unroll
            for (int mi = 0; mi < 2; mi++)
#pragma unroll
                for (int nj = 0; nj < 8; nj++)
                    mma_bf16(acc[mi][nj], a[0][mi], b[0][nj]);
#pragma unroll
            for (int mi = 0; mi < 2; mi++)
#pragma unroll
                for (int nj = 0; nj < 8; nj++)
                    mma_bf16(acc[mi][nj], a[0][mi], b[1][nj]);
#pragma unroll
            for (int mi = 0; mi < 2; mi++)
#pragma unroll
                for (int nj = 0; nj < 8; nj++)
                    mma_bf16(acc[mi][nj], a[1][mi], b[0][nj]);
        }
        if (ch + 3 < 64)
            ld_stage(sb + ((ch + 3) & 3)*STG_B, Ah, Al, Bh, Bl,
                     m0, n0, (ch + 3)*32, tid);
    }
}

// ---------------- single-pass fp16 mainloop ----------------------------------
__device__ __forceinline__ void hmma_mainloop_f16(
    const __half* A, const __half* Bm,
    int m0, int n0, uint32_t sb, float acc[2][8][4])
{
    const int tid = threadIdx.x, lane = tid & 31, w = tid >> 5;
#pragma unroll
    for (int i = 0; i < 2; i++)
#pragma unroll
        for (int j = 0; j < 8; j++)
#pragma unroll
            for (int k = 0; k < 4; k++) acc[i][j][k] = 0.f;

    ld_stage_f16(sb,            A, Bm, m0, n0, 0,  tid);
    ld_stage_f16(sb +   FSTG_B, A, Bm, m0, n0, 32, tid);
    ld_stage_f16(sb + 2*FSTG_B, A, Bm, m0, n0, 64, tid);

    const int arow = (w >> 1)*32 + (lane & 15);
    const int brow = (w & 1)*32 + (lane & 15);
    const int fcol = (lane >> 4) << 4;

    for (int ch = 0; ch < 64; ch++) {
        if (ch < 62)       asm volatile("cp.async.wait_group 2;" ::: "memory");
        else if (ch == 62) asm volatile("cp.async.wait_group 1;" ::: "memory");
        else               asm volatile("cp.async.wait_group 0;" ::: "memory");
        __syncthreads();
        uint32_t s0 = sb + (ch & 3)*FSTG_B;
#pragma unroll
        for (int kk = 0; kk < 2; kk++) {
            int kB = kk*32 + fcol;
            uint32_t a[2][4], b[8][2];
#pragma unroll
            for (int mi = 0; mi < 2; mi++)
                LDM4(a[mi], s0 + (arow + mi*16)*RSTR + kB);
#pragma unroll
            for (int p = 0; p < 4; p++) {
                int r = brow + (p & 1)*16 + ((p & 2) ? 64 : 0);
                uint32_t q[4];
                LDM4(q, s0 + REG_B + r*RSTR + kB);
                b[2*p][0]   = q[0]; b[2*p][1]   = q[2];
                b[2*p+1][0] = q[1]; b[2*p+1][1] = q[3];
            }
#pragma unroll
            for (int mi = 0; mi < 2; mi++)
#pragma unroll
                for (int nj = 0; nj < 8; nj++)
                    mma_f16(acc[mi][nj], a[mi], b[nj][0], b[nj][1]);
        }
        if (ch + 3 < 64)
            ld_stage_f16(sb + ((ch + 3) & 3)*FSTG_B, A, Bm, m0, n0,
                         (ch + 3)*32, tid);
    }
}

// ---------------- Q/K projection + bias + RoPE -> bf16 splits ---------------
// grid (32, 32): x -> z = x>>4 (q/k), nh = x&15 ; y -> m-tile
__global__ __launch_bounds__(256, 1)
void gemm_qkv_tc(const float* __restrict__ bq, const float* __restrict__ bk)
{
    extern __shared__ char dsm[];
    uint32_t sb = smem_u32(dsm);
    const int tid = threadIdx.x, lane = tid & 31, w = tid >> 5;
    const int z = blockIdx.x >> 4, nh = blockIdx.x & 15;
    const int m0 = blockIdx.y * 128, n0 = nh * 128;
    const float* bias = (z == 0) ? bq : bk;
    const __nv_bfloat16* Bh = g_Bh + (size_t)z * H_ * H_;
    const __nv_bfloat16* Bl = g_Bl + (size_t)z * H_ * H_;

    float acc[2][8][4];
    hmma_mainloop(g_Ah, g_Al, Bh, Bl, m0, n0, sb, acc);

    const int gr = lane >> 2, gc = (lane & 3)*2;
    __nv_bfloat16* oh = (z == 0) ? g_qh : g_kh;
    __nv_bfloat16* ol = (z == 0) ? g_ql : g_kl;
#pragma unroll
    for (int mi = 0; mi < 2; mi++)
#pragma unroll
        for (int h = 0; h < 2; h++) {
            int m = m0 + (w >> 1)*32 + mi*16 + gr + h*8;
            int bb = m >> 11, s = m & 2047;
#pragma unroll
            for (int nj = 0; nj < 4; nj++) {
                int c = (w & 1)*32 + nj*8 + gc;
                float vl0 = acc[mi][nj][h*2+0]   + bias[n0 + c];
                float vl1 = acc[mi][nj][h*2+1]   + bias[n0 + c + 1];
                float vh0 = acc[mi][nj+4][h*2+0] + bias[n0 + 64 + c];
                float vh1 = acc[mi][nj+4][h*2+1] + bias[n0 + 64 + c + 1];
                float cs0 = g_cos[s*64 + c],     sn0 = g_sin[s*64 + c];
                float cs1 = g_cos[s*64 + c + 1], sn1 = g_sin[s*64 + c + 1];
                float o0 = vl0*cs0 - vh0*sn0, o2 = vh0*cs0 + vl0*sn0;
                float o1 = vl1*cs1 - vh1*sn1, o3 = vh1*cs1 + vl1*sn1;
                size_t base = ((size_t)(bb*NH_ + nh)*S_ + s) * HD_;
                *(uint32_t*)&oh[base + c]      = packbf(o0, o1);
                *(uint32_t*)&ol[base + c]      = packbf(rlo(o0), rlo(o1));
                *(uint32_t*)&oh[base + 64 + c] = packbf(o2, o3);
                *(uint32_t*)&ol[base + 64 + c] = packbf(rlo(o2), rlo(o3));
            }
        }
}

// ---------------- V projection (fp16 single-pass) -> transposed splits ------
__global__ __launch_bounds__(256, 1)
void gemm_v_f16(const float* __restrict__ bv)
{
    extern __shared__ char dsm[];
    uint32_t sb = smem_u32(dsm);
    const int tid = threadIdx.x, lane = tid & 31, w = tid >> 5;
    const int nh = blockIdx.x;
    const int m0 = blockIdx.y * 128, n0 = nh * 128;

    float acc[2][8][4];
    hmma_mainloop_f16(g_Af, g_Bf, m0, n0, sb, acc);

    const int gr = lane >> 2, gc = (lane & 3)*2;
#pragma unroll
    for (int mi = 0; mi < 2; mi++)
#pragma unroll
        for (int h = 0; h < 2; h++) {
            int m = m0 + (w >> 1)*32 + mi*16 + gr + h*8;
            int bb = m >> 11, s = m & 2047;
            size_t vb = (size_t)(bb*NH_ + nh) * HD_;
#pragma unroll
            for (int nj = 0; nj < 4; nj++) {
                int c = (w & 1)*32 + nj*8 + gc;
                float vv[4] = {acc[mi][nj][h*2+0]   + bv[n0 + c],
                               acc[mi][nj][h*2+1]   + bv[n0 + c + 1],
                               acc[mi][nj+4][h*2+0] + bv[n0 + 64 + c],
                               acc[mi][nj+4][h*2+1] + bv[n0 + 64 + c + 1]};
                int   cc[4] = {c, c + 1, 64 + c, 64 + c + 1};
#pragma unroll
                for (int u = 0; u < 4; u++) {
                    g_vth[(vb + cc[u])*S_ + s] = __float2bfloat16_rn(vv[u]);
                    g_vtl[(vb + cc[u])*S_ + s] = __float2bfloat16_rn(rlo(vv[u]));
                }
            }
        }
}

// ---------------- output projection (fp16 single-pass) ----------------------
__global__ __launch_bounds__(256, 1)
void gemm_out_f16(const float* __restrict__ bo, float* __restrict__ out)
{
    extern __shared__ char dsm[];
    uint32_t sb = smem_u32(dsm);
    const int tid = threadIdx.x, lane = tid & 31, w = tid >> 5;
    const int m0 = blockIdx.y * 128, n0 = blockIdx.x * 128;

    float acc[2][8][4];
    hmma_mainloop_f16(g_Af, g_Wf, m0, n0, sb, acc);

    const int gr = lane >> 2, gc = (lane & 3)*2;
#pragma unroll
    for (int mi = 0; mi < 2; mi++)
#pragma unroll
        for (int h = 0; h < 2; h++) {
            int m = m0 + (w >> 1)*32 + mi*16 + gr + h*8;
            float* op = out + (size_t)m * H_ + n0;
#pragma unroll
            for (int nj = 0; nj < 4; nj++) {
                int c = (w & 1)*32 + nj*8 + gc;
                *(float2*)&op[c] = make_float2(
                    acc[mi][nj][h*2+0] + bo[n0 + c],
                    acc[mi][nj][h*2+1] + bo[n0 + c + 1]);
                *(float2*)&op[64 + c] = make_float2(
                    acc[mi][nj+4][h*2+0] + bo[n0 + 64 + c],
                    acc[mi][nj+4][h*2+1] + bo[n0 + 64 + c + 1]);
            }
        }
}

// ---------------- tensor-core causal flash attention (unchanged) ------------
#define ASTR 272
#define ARGN (128*ASTR)
#define SMEM_AT (6*ARGN)

__device__ __forceinline__ void attn_ld(uint32_t dst,
    const __nv_bfloat16* __restrict__ src, int stride, int tid)
{
#pragma unroll
    for (int it = 0; it < 8; it++) {
        int idx = tid + it*256;
        int r = idx >> 4, c = idx & 15;
        CP16(dst + r*ASTR + c*16, (const void*)(src + (size_t)r*stride + c*8));
    }
}

__global__ __launch_bounds__(256, 1)
void attn_tc_kernel()
{
    extern __shared__ char dsm[];
    uint32_t sb = smem_u32(dsm);
    const int tid = threadIdx.x, lane = tid & 31, wm = tid >> 5;
    const int gr = lane >> 2, gc = (lane & 3)*2;
    const int bh = blockIdx.y;
    const int iq = (int)gridDim.x - 1 - (int)blockIdx.x;
    const int laneoff = (lane & 15)*ASTR + (lane >> 4)*16;
    const float scale = 0.08838834764831845f;

    const size_t qkbase = (size_t)bh * S_ * HD_;
    const __nv_bfloat16* Qh = g_qh + qkbase + (size_t)iq*128*HD_;
    const __nv_bfloat16* Ql = g_ql + qkbase + (size_t)iq*128*HD_;
    const size_t vbase = (size_t)bh * HD_ * S_;

    attn_ld(sb + 0*ARGN, Qh, HD_, tid);
    attn_ld(sb + 1*ARGN, Ql, HD_, tid);
    CP_COMMIT();
    attn_ld(sb + 2*ARGN, g_kh + qkbase, HD_, tid);
    attn_ld(sb + 3*ARGN, g_kl + qkbase, HD_, tid);
    CP_COMMIT();
    attn_ld(sb + 4*ARGN, g_vth + vbase, S_, tid);
    attn_ld(sb + 5*ARGN, g_vtl + vbase, S_, tid);
    CP_COMMIT();

    const uint32_t qhb = sb + 0*ARGN + wm*16*ASTR + laneoff;
    const uint32_t qlb = sb + 1*ARGN + wm*16*ASTR + laneoff;
    const uint32_t khb = sb + 2*ARGN + laneoff;
    const uint32_t klb = sb + 3*ARGN + laneoff;
    const uint32_t vhb = sb + 4*ARGN + laneoff;
    const uint32_t vlb = sb + 5*ARGN + laneoff;

    float O[16][4];
#pragma unroll
    for (int j = 0; j < 16; j++)
#pragma unroll
        for (int k = 0; k < 4; k++) O[j][k] = 0.f;
    float m0r = -1e30f, m1r = -1e30f, l0r = 0.f, l1r = 0.f;

    for (int jt = 0; jt <= iq; jt++) {
        asm volatile("cp.async.wait_group 1;" ::: "memory");
        __syncthreads();

        float Sf[16][4];
#pragma unroll
        for (int j = 0; j < 16; j++)
#pragma unroll
            for (int k = 0; k < 4; k++) Sf[j][k] = 0.f;
#pragma unroll
        for (int t = 0; t < 8; t++) {
            uint32_t ah[4], al[4];
            LDM4(ah, qhb + t*32);
            LDM4(al, qlb + t*32);
#pragma unroll
            for (int jp = 0; jp < 8; jp++) {
                uint32_t bh4[4], bl4[4];
                LDM4(bh4, khb + jp*16*ASTR + t*32);
                LDM4(bl4, klb + jp*16*ASTR + t*32);
                mma2(Sf[2*jp],   ah, bh4[0], bh4[2]);
                mma2(Sf[2*jp+1], ah, bh4[1], bh4[3]);
                mma2(Sf[2*jp],   ah, bl4[0], bl4[2]);
                mma2(Sf[2*jp+1], ah, bl4[1], bl4[3]);
                mma2(Sf[2*jp],   al, bh4[0], bh4[2]);
                mma2(Sf[2*jp+1], al, bh4[1], bh4[3]);
            }
        }
        __syncthreads();
        if (jt < iq) {
            attn_ld(sb + 2*ARGN, g_kh + qkbase + (size_t)(jt+1)*128*HD_, HD_, tid);
            attn_ld(sb + 3*ARGN, g_kl + qkbase + (size_t)(jt+1)*128*HD_, HD_, tid);
            CP_COMMIT();
        }

        const int r0 = wm*16 + gr, r1 = r0 + 8;
        if (jt == iq) {
#pragma unroll
            for (int j = 0; j < 16; j++) {
                int cA = j*8 + gc, cB = cA + 1;
                Sf[j][0] = (cA > r0) ? -1e30f : Sf[j][0]*scale;
                Sf[j][1] = (cB > r0) ? -1e30f : Sf[j][1]*scale;
                Sf[j][2] = (cA > r1) ? -1e30f : Sf[j][2]*scale;
                Sf[j][3] = (cB > r1) ? -1e30f : Sf[j][3]*scale;
            }
        } else {
#pragma unroll
            for (int j = 0; j < 16; j++)
#pragma unroll
                for (int k = 0; k < 4; k++) Sf[j][k] *= scale;
        }

        float mx0 = -1e30f, mx1 = -1e30f;
#pragma unroll
        for (int j = 0; j < 16; j++) {
            mx0 = fmaxf(mx0, fmaxf(Sf[j][0], Sf[j][1]));
            mx1 = fmaxf(mx1, fmaxf(Sf[j][2], Sf[j][3]));
        }
        mx0 = fmaxf(mx0, __shfl_xor_sync(0xffffffffu, mx0, 1));
        mx0 = fmaxf(mx0, __shfl_xor_sync(0xffffffffu, mx0, 2));
        mx1 = fmaxf(mx1, __shfl_xor_sync(0xffffffffu, mx1, 1));
        mx1 = fmaxf(mx1, __shfl_xor_sync(0xffffffffu, mx1, 2));
        float mn0 = fmaxf(m0r, mx0), mn1 = fmaxf(m1r, mx1);
        float al0 = __expf(m0r - mn0), al1 = __expf(m1r - mn1);
        m0r = mn0; m1r = mn1;
        float sum0 = 0.f, sum1 = 0.f;
#pragma unroll
        for (int j = 0; j < 16; j++) {
            Sf[j][0] = __expf(Sf[j][0] - mn0); sum0 += Sf[j][0];
            Sf[j][1] = __expf(Sf[j][1] - mn0); sum0 += Sf[j][1];
            Sf[j][2] = __expf(Sf[j][2] - mn1); sum1 += Sf[j][2];
            Sf[j][3] = __expf(Sf[j][3] - mn1); sum1 += Sf[j][3];
        }
        sum0 += __shfl_xor_sync(0xffffffffu, sum0, 1);
        sum0 += __shfl_xor_sync(0xffffffffu, sum0, 2);
        sum1 += __shfl_xor_sync(0xffffffffu, sum1, 1);
        sum1 += __shfl_xor_sync(0xffffffffu, sum1, 2);
        l0r = l0r*al0 + sum0; l1r = l1r*al1 + sum1;
#pragma unroll
        for (int j = 0; j < 16; j++) {
            O[j][0] *= al0; O[j][1] *= al0;
            O[j][2] *= al1; O[j][3] *= al1;
        }

        asm volatile("cp.async.wait_group 1;" ::: "memory");
        __syncthreads();

#pragma unroll
        for (int t = 0; t < 8; t++) {
            uint32_t aPh[4], aPl[4];
            aPh[0] = packbf(Sf[2*t][0],   Sf[2*t][1]);
            aPh[1] = packbf(Sf[2*t][2],   Sf[2*t][3]);
            aPh[2] = packbf(Sf[2*t+1][0], Sf[2*t+1][1]);
            aPh[3] = packbf(Sf[2*t+1][2], Sf[2*t+1][3]);
            aPl[0] = packbf(rlo(Sf[2*t][0]),   rlo(Sf[2*t][1]));
            aPl[1] = packbf(rlo(Sf[2*t][2]),   rlo(Sf[2*t][3]));
            aPl[2] = packbf(rlo(Sf[2*t+1][0]), rlo(Sf[2*t+1][1]));
            aPl[3] = packbf(rlo(Sf[2*t+1][2]), rlo(Sf[2*t+1][3]));
#pragma unroll
            for (int jp = 0; jp < 8; jp++) {
                uint32_t bh4[4], bl4[4];
                LDM4(bh4, vhb + jp*16*ASTR + t*32);
                LDM4(bl4, vlb + jp*16*ASTR + t*32);
                mma2(O[2*jp],   aPh, bh4[0], bh4[2]);
                mma2(O[2*jp+1], aPh, bh4[1], bh4[3]);
                mma2(O[2*jp],   aPl, bh4[0], bh4[2]);
                mma2(O[2*jp+1], aPl, bh4[1], bh4[3]);
                mma2(O[2*jp],   aPh, bl4[0], bl4[2]);
                mma2(O[2*jp+1], aPh, bl4[1], bl4[3]);
            }
        }
        __syncthreads();
        if (jt < iq) {
            attn_ld(sb + 4*ARGN, g_vth + vbase + (size_t)(jt+1)*128, S_, tid);
            attn_ld(sb + 5*ARGN, g_vtl + vbase + (size_t)(jt+1)*128, S_, tid);
            CP_COMMIT();
        }
    }

    const int b = bh >> 4, nh = bh & 15;
    float inv0 = 1.f / l0r, inv1 = 1.f / l1r;
    size_t row0 = (size_t)(b*S_ + iq*128 + wm*16 + gr);
#pragma unroll
    for (int j = 0; j < 16; j++) {
        int col = nh*HD_ + j*8 + gc;
        *(float2*)&g_attn[row0*H_ + col] =
            make_float2(O[j][0]*inv0, O[j][1]*inv0);
        *(float2*)&g_attn[(row0 + 8)*H_ + col] =
            make_float2(O[j][2]*inv1, O[j][3]*inv1);
    }
}

// ---------------- launch ----------------------------------------------------
extern "C" void kernel_launch(void* const* d_in, const int* in_sizes, int n_in,
                              void* d_out, int out_size)
{
    (void)in_sizes; (void)n_in; (void)out_size;
    const float* X  = (const float*)d_in[0];
    const float* Wq = (const float*)d_in[2];
    const float* bq = (const float*)d_in[3];
    const float* Wk = (const float*)d_in[4];
    const float* bk = (const float*)d_in[5];
    const float* Wv = (const float*)d_in[6];
    const float* bv = (const float*)d_in[7];
    const float* Wo = (const float*)d_in[8];
    const float* bo = (const float*)d_in[9];
    float* out = (float*)d_out;

    rope_table_kernel<<<(S_*64 + 255)/256, 256>>>();
    convert_split_kernel<<<M_*H_/1024, 256>>>(X, 0);
    dim3 tb(32, 8), tg(H_/32, H_/32);
    transpose_split_kernel<<<tg, tb>>>(Wq, 0);
    transpose_split_kernel<<<tg, tb>>>(Wk, 1);
    transpose_split_kernel<<<tg, tb>>>(Wv, 2);
    transpose_split_kernel<<<tg, tb>>>(Wo, 3);

    cudaFuncSetAttribute(gemm_qkv_tc, cudaFuncAttributeMaxDynamicSharedMemorySize,
                         SMEM_GG);
    gemm_qkv_tc<<<dim3(32, 32), 256, SMEM_GG>>>(bq, bk);

    cudaFuncSetAttribute(gemm_v_f16, cudaFuncAttributeMaxDynamicSharedMemorySize,
                         SMEM_GF);
    gemm_v_f16<<<dim3(16, 32), 256, SMEM_GF>>>(bv);

    cudaFuncSetAttribute(attn_tc_kernel, cudaFuncAttributeMaxDynamicSharedMemorySize,
                         SMEM_AT);
    attn_tc_kernel<<<dim3(S_/128, B_*NH_), 256, SMEM_AT>>>();

    convert_split_kernel<<<M_*H_/1024, 256>>>(nullptr, 1);
    cudaFuncSetAttribute(gemm_out_f16, cudaFuncAttributeMaxDynamicSharedMemorySize,
                         SMEM_GF);
    gemm_out_f16<<<dim3(16, 32), 256, SMEM_GF>>>(bo, out);
}

// round 8
// speedup vs baseline: 4.4640x; 1.6408x over previous
#include <cuda_runtime.h>
#include <cuda_bf16.h>
#include <cuda_fp16.h>
#include <math.h>
#include <stdint.h>

#define B_  2
#define S_  2048
#define H_  2048
#define NH_ 16
#define HD_ 128
#define M_  (B_*S_)   // 4096

// ---------------- scratch (device globals) ---------------------------------
__device__ float g_attn[M_*H_];
__device__ float g_cos[S_*64];
__device__ float g_sin[S_*64];

__device__ __align__(16) __half g_Af[M_*H_];          // activations fp16
__device__ __align__(16) __half g_Bqk[2*H_*H_];       // Wq^T, Wk^T fp16
__device__ __align__(16) __half g_Bf[H_*H_];          // Wv^T fp16
__device__ __align__(16) __half g_Wf[H_*H_];          // Wo^T fp16

// attention operands
__device__ __align__(16) __half g_qf[B_*NH_*S_*HD_];  // roped Q fp16
__device__ __align__(16) __half g_kf[B_*NH_*S_*HD_];  // roped K fp16
__device__ __align__(16) __nv_bfloat16 g_vth[B_*NH_*HD_*S_], g_vtl[B_*NH_*HD_*S_];

// ---------------- PTX helpers ----------------------------------------------
__device__ __forceinline__ uint32_t smem_u32(const void* p) {
    uint32_t a;
    asm("{ .reg .u64 t; cvta.to.shared.u64 t, %1; cvt.u32.u64 %0, t; }"
        : "=r"(a) : "l"(p));
    return a;
}
#define CP16(dst, src) \
    asm volatile("cp.async.cg.shared.global [%0], [%1], 16;" \
                 :: "r"(dst), "l"(src) : "memory")
#define CP_COMMIT() asm volatile("cp.async.commit_group;" ::: "memory")

#define LDM4(r, addr) \
    asm volatile("ldmatrix.sync.aligned.m8n8.x4.shared.b16 {%0,%1,%2,%3}, [%4];" \
        : "=r"((r)[0]), "=r"((r)[1]), "=r"((r)[2]), "=r"((r)[3]) : "r"(addr))

__device__ __forceinline__ void mma_f16(float* d, const uint32_t* a,
                                        uint32_t b0, uint32_t b1) {
    asm volatile("mma.sync.aligned.m16n8k16.row.col.f32.f16.f16.f32 "
        "{%0,%1,%2,%3}, {%4,%5,%6,%7}, {%8,%9}, {%0,%1,%2,%3};"
        : "+f"(d[0]), "+f"(d[1]), "+f"(d[2]), "+f"(d[3])
        : "r"(a[0]), "r"(a[1]), "r"(a[2]), "r"(a[3]), "r"(b0), "r"(b1));
}
__device__ __forceinline__ void mma2(float* d, const uint32_t* a,
                                     uint32_t b0, uint32_t b1) {
    asm volatile("mma.sync.aligned.m16n8k16.row.col.f32.bf16.bf16.f32 "
        "{%0,%1,%2,%3}, {%4,%5,%6,%7}, {%8,%9}, {%0,%1,%2,%3};"
        : "+f"(d[0]), "+f"(d[1]), "+f"(d[2]), "+f"(d[3])
        : "r"(a[0]), "r"(a[1]), "r"(a[2]), "r"(a[3]), "r"(b0), "r"(b1));
}
__device__ __forceinline__ uint32_t packbf(float x, float y) {
    __nv_bfloat162 t = __floats2bfloat162_rn(x, y);
    return *(uint32_t*)&t;
}
__device__ __forceinline__ uint32_t packhf(float x, float y) {
    __half2 t = __floats2half2_rn(x, y);
    return *(uint32_t*)&t;
}
__device__ __forceinline__ float rlo(float x) {
    return x - __bfloat162float(__float2bfloat16_rn(x));
}

// ---------------- prep kernels ---------------------------------------------
__global__ void rope_table_kernel()
{
    int idx = blockIdx.x * blockDim.x + threadIdx.x;
    if (idx >= S_ * 64) return;
    int s = idx >> 6, p = idx & 63;
    double invf = exp(-log(10000.0) * (double)p / 64.0);
    double ang  = (double)s * invf;
    g_cos[idx] = (float)cos(ang);
    g_sin[idx] = (float)sin(ang);
}

// fp32 -> fp16 (g_Af). src_sel: 0 -> param, 1 -> g_attn
__global__ void convert_f16_kernel(const float* __restrict__ in, int src_sel)
{
    const float* src = src_sel ? g_attn : in;
    int i = (blockIdx.x * blockDim.x + threadIdx.x) * 4;
    float4 v = *(const float4*)&src[i];
    *(ushort4*)((unsigned short*)g_Af + i) = make_ushort4(
        __half_as_ushort(__float2half_rn(v.x)),
        __half_as_ushort(__float2half_rn(v.y)),
        __half_as_ushort(__float2half_rn(v.z)),
        __half_as_ushort(__float2half_rn(v.w)));
}

// W [2048,2048] -> W^T fp16. which: 0,1 -> g_Bqk slab; 2 -> g_Bf; 3 -> g_Wf
__global__ void transpose_f16_kernel(const float* __restrict__ in, int which)
{
    __half* dst = (which < 2) ? g_Bqk + (size_t)which*H_*H_
                : (which == 2) ? g_Bf : g_Wf;
    __shared__ float t[32][33];
    int tx = threadIdx.x, ty = threadIdx.y;
    int c0 = blockIdx.x * 32, r0 = blockIdx.y * 32;
#pragma unroll
    for (int k = 0; k < 4; k++)
        t[ty + 8*k][tx] = in[(size_t)(r0 + ty + 8*k) * H_ + c0 + tx];
    __syncthreads();
#pragma unroll
    for (int k = 0; k < 4; k++)
        dst[(size_t)(c0 + ty + 8*k) * H_ + r0 + tx] =
            __float2half_rn(t[tx][ty + 8*k]);
}

// ---------------- fp16 GEMM mainloop ----------------------------------------
#define RSTR   80
#define REG_B  (128*RSTR)        // 10240
#define FSTG_B (2*REG_B)         // fp16 stage: A|B
#define SMEM_GF (4*FSTG_B)       // 81920

__device__ __forceinline__ void ld_region(uint32_t dst,
    const __half* __restrict__ src, int row0, int kb, int tid)
{
#pragma unroll
    for (int it = 0; it < 2; it++) {
        int idx = tid + it*256;
        int r = idx >> 2, c = idx & 3;
        CP16(dst + r*RSTR + c*16,
             (const void*)(src + (size_t)(row0 + r) * H_ + kb + c*8));
    }
}
__device__ __forceinline__ void ld_stage_f16(uint32_t s0,
    const __half* A, const __half* Bm, int m0, int n0, int kb, int tid)
{
    ld_region(s0,         A,  m0, kb, tid);
    ld_region(s0 + REG_B, Bm, n0, kb, tid);
    CP_COMMIT();
}

__device__ __forceinline__ void hmma_mainloop_f16(
    const __half* A, const __half* Bm,
    int m0, int n0, uint32_t sb, float acc[2][8][4])
{
    const int tid = threadIdx.x, lane = tid & 31, w = tid >> 5;
#pragma unroll
    for (int i = 0; i < 2; i++)
#pragma unroll
        for (int j = 0; j < 8; j++)
#pragma unroll
            for (int k = 0; k < 4; k++) acc[i][j][k] = 0.f;

    ld_stage_f16(sb,            A, Bm, m0, n0, 0,  tid);
    ld_stage_f16(sb +   FSTG_B, A, Bm, m0, n0, 32, tid);
    ld_stage_f16(sb + 2*FSTG_B, A, Bm, m0, n0, 64, tid);

    const int arow = (w >> 1)*32 + (lane & 15);
    const int brow = (w & 1)*32 + (lane & 15);
    const int fcol = (lane >> 4) << 4;

    for (int ch = 0; ch < 64; ch++) {
        if (ch < 62)       asm volatile("cp.async.wait_group 2;" ::: "memory");
        else if (ch == 62) asm volatile("cp.async.wait_group 1;" ::: "memory");
        else               asm volatile("cp.async.wait_group 0;" ::: "memory");
        __syncthreads();
        uint32_t s0 = sb + (ch & 3)*FSTG_B;
#pragma unroll
        for (int kk = 0; kk < 2; kk++) {
            int kB = kk*32 + fcol;
            uint32_t a[2][4], b[8][2];
#pragma unroll
            for (int mi = 0; mi < 2; mi++)
                LDM4(a[mi], s0 + (arow + mi*16)*RSTR + kB);
#pragma unroll
            for (int p = 0; p < 4; p++) {
                int r = brow + (p & 1)*16 + ((p & 2) ? 64 : 0);
                uint32_t q[4];
                LDM4(q, s0 + REG_B + r*RSTR + kB);
                b[2*p][0]   = q[0]; b[2*p][1]   = q[2];
                b[2*p+1][0] = q[1]; b[2*p+1][1] = q[3];
            }
#pragma unroll
            for (int mi = 0; mi < 2; mi++)
#pragma unroll
                for (int nj = 0; nj < 8; nj++)
                    mma_f16(acc[mi][nj], a[mi], b[nj][0], b[nj][1]);
        }
        if (ch + 3 < 64)
            ld_stage_f16(sb + ((ch + 3) & 3)*FSTG_B, A, Bm, m0, n0,
                         (ch + 3)*32, tid);
    }
}

// ---------------- Q/K projection + bias + RoPE -> fp16 ----------------------
// grid (32, 32): x -> z = x>>4 (q/k), nh = x&15 ; y -> m-tile
__global__ __launch_bounds__(256, 1)
void gemm_qk_f16(const float* __restrict__ bq, const float* __restrict__ bk)
{
    extern __shared__ char dsm[];
    uint32_t sb = smem_u32(dsm);
    const int tid = threadIdx.x, lane = tid & 31, w = tid >> 5;
    const int z = blockIdx.x >> 4, nh = blockIdx.x & 15;
    const int m0 = blockIdx.y * 128, n0 = nh * 128;
    const float* bias = (z == 0) ? bq : bk;

    float acc[2][8][4];
    hmma_mainloop_f16(g_Af, g_Bqk + (size_t)z*H_*H_, m0, n0, sb, acc);

    const int gr = lane >> 2, gc = (lane & 3)*2;
    __half* oq = (z == 0) ? g_qf : g_kf;
#pragma unroll
    for (int mi = 0; mi < 2; mi++)
#pragma unroll
        for (int h = 0; h < 2; h++) {
            int m = m0 + (w >> 1)*32 + mi*16 + gr + h*8;
            int bb = m >> 11, s = m & 2047;
            size_t base = ((size_t)(bb*NH_ + nh)*S_ + s) * HD_;
#pragma unroll
            for (int nj = 0; nj < 4; nj++) {
                int c = (w & 1)*32 + nj*8 + gc;
                float vl0 = acc[mi][nj][h*2+0]   + bias[n0 + c];
                float vl1 = acc[mi][nj][h*2+1]   + bias[n0 + c + 1];
                float vh0 = acc[mi][nj+4][h*2+0] + bias[n0 + 64 + c];
                float vh1 = acc[mi][nj+4][h*2+1] + bias[n0 + 64 + c + 1];
                float cs0 = g_cos[s*64 + c],     sn0 = g_sin[s*64 + c];
                float cs1 = g_cos[s*64 + c + 1], sn1 = g_sin[s*64 + c + 1];
                *(uint32_t*)&oq[base + c] =
                    packhf(vl0*cs0 - vh0*sn0, vl1*cs1 - vh1*sn1);
                *(uint32_t*)&oq[base + 64 + c] =
                    packhf(vh0*cs0 + vl0*sn0, vh1*cs1 + vl1*sn1);
            }
        }
}

// ---------------- V projection (fp16) -> transposed bf16 splits -------------
__global__ __launch_bounds__(256, 1)
void gemm_v_f16(const float* __restrict__ bv)
{
    extern __shared__ char dsm[];
    uint32_t sb = smem_u32(dsm);
    const int tid = threadIdx.x, lane = tid & 31, w = tid >> 5;
    const int nh = blockIdx.x;
    const int m0 = blockIdx.y * 128, n0 = nh * 128;

    float acc[2][8][4];
    hmma_mainloop_f16(g_Af, g_Bf, m0, n0, sb, acc);

    const int gr = lane >> 2, gc = (lane & 3)*2;
#pragma unroll
    for (int mi = 0; mi < 2; mi++)
#pragma unroll
        for (int h = 0; h < 2; h++) {
            int m = m0 + (w >> 1)*32 + mi*16 + gr + h*8;
            int bb = m >> 11, s = m & 2047;
            size_t vb = (size_t)(bb*NH_ + nh) * HD_;
#pragma unroll
            for (int nj = 0; nj < 4; nj++) {
                int c = (w & 1)*32 + nj*8 + gc;
                float vv[4] = {acc[mi][nj][h*2+0]   + bv[n0 + c],
                               acc[mi][nj][h*2+1]   + bv[n0 + c + 1],
                               acc[mi][nj+4][h*2+0] + bv[n0 + 64 + c],
                               acc[mi][nj+4][h*2+1] + bv[n0 + 64 + c + 1]};
                int   cc[4] = {c, c + 1, 64 + c, 64 + c + 1};
#pragma unroll
                for (int u = 0; u < 4; u++) {
                    g_vth[(vb + cc[u])*S_ + s] = __float2bfloat16_rn(vv[u]);
                    g_vtl[(vb + cc[u])*S_ + s] = __float2bfloat16_rn(rlo(vv[u]));
                }
            }
        }
}

// ---------------- output projection (fp16) ----------------------------------
__global__ __launch_bounds__(256, 1)
void gemm_out_f16(const float* __restrict__ bo, float* __restrict__ out)
{
    extern __shared__ char dsm[];
    uint32_t sb = smem_u32(dsm);
    const int tid = threadIdx.x, lane = tid & 31, w = tid >> 5;
    const int m0 = blockIdx.y * 128, n0 = blockIdx.x * 128;

    float acc[2][8][4];
    hmma_mainloop_f16(g_Af, g_Wf, m0, n0, sb, acc);

    const int gr = lane >> 2, gc = (lane & 3)*2;
#pragma unroll
    for (int mi = 0; mi < 2; mi++)
#pragma unroll
        for (int h = 0; h < 2; h++) {
            int m = m0 + (w >> 1)*32 + mi*16 + gr + h*8;
            float* op = out + (size_t)m * H_ + n0;
#pragma unroll
            for (int nj = 0; nj < 4; nj++) {
                int c = (w & 1)*32 + nj*8 + gc;
                *(float2*)&op[c] = make_float2(
                    acc[mi][nj][h*2+0] + bo[n0 + c],
                    acc[mi][nj][h*2+1] + bo[n0 + c + 1]);
                *(float2*)&op[64 + c] = make_float2(
                    acc[mi][nj+4][h*2+0] + bo[n0 + 64 + c],
                    acc[mi][nj+4][h*2+1] + bo[n0 + 64 + c + 1]);
            }
        }
}

// ---------------- tensor-core causal flash attention ------------------------
// regions: 0 Qf(fp16) 1 Kf(fp16) 2 Vh(bf16) 3 Vl(bf16)
#define ASTR 272
#define ARGN (128*ASTR)
#define SMEM_AT (4*ARGN)         // 139264

__device__ __forceinline__ void attn_ld(uint32_t dst,
    const void* __restrict__ src_, int stride, int tid)
{
    const __half* src = (const __half*)src_;
#pragma unroll
    for (int it = 0; it < 8; it++) {
        int idx = tid + it*256;
        int r = idx >> 4, c = idx & 15;
        CP16(dst + r*ASTR + c*16, (const void*)(src + (size_t)r*stride + c*8));
    }
}

__global__ __launch_bounds__(256, 1)
void attn_tc_kernel()
{
    extern __shared__ char dsm[];
    uint32_t sb = smem_u32(dsm);
    const int tid = threadIdx.x, lane = tid & 31, wm = tid >> 5;
    const int gr = lane >> 2, gc = (lane & 3)*2;
    const int bh = blockIdx.y;
    const int iq = (int)gridDim.x - 1 - (int)blockIdx.x;
    const int laneoff = (lane & 15)*ASTR + (lane >> 4)*16;
    const float scale = 0.08838834764831845f;

    const size_t qkbase = (size_t)bh * S_ * HD_;
    const size_t vbase  = (size_t)bh * HD_ * S_;

    attn_ld(sb + 0*ARGN, g_qf + qkbase + (size_t)iq*128*HD_, HD_, tid);
    CP_COMMIT();
    attn_ld(sb + 1*ARGN, g_kf + qkbase, HD_, tid);
    CP_COMMIT();
    attn_ld(sb + 2*ARGN, g_vth + vbase, S_, tid);
    attn_ld(sb + 3*ARGN, g_vtl + vbase, S_, tid);
    CP_COMMIT();

    const uint32_t qfb = sb + 0*ARGN + wm*16*ASTR + laneoff;
    const uint32_t kfb = sb + 1*ARGN + laneoff;
    const uint32_t vhb = sb + 2*ARGN + laneoff;
    const uint32_t vlb = sb + 3*ARGN + laneoff;

    float O[16][4];
#pragma unroll
    for (int j = 0; j < 16; j++)
#pragma unroll
        for (int k = 0; k < 4; k++) O[j][k] = 0.f;
    float m0r = -1e30f, m1r = -1e30f, l0r = 0.f, l1r = 0.f;

    for (int jt = 0; jt <= iq; jt++) {
        asm volatile("cp.async.wait_group 1;" ::: "memory");
        __syncthreads();                       // Q + K(jt) ready

        // ---- S = Q K^T (fp16 single-pass) ----
        float Sf[16][4];
#pragma unroll
        for (int j = 0; j < 16; j++)
#pragma unroll
            for (int k = 0; k < 4; k++) Sf[j][k] = 0.f;
#pragma unroll
        for (int t = 0; t < 8; t++) {
            uint32_t a[4];
            LDM4(a, qfb + t*32);
#pragma unroll
            for (int jp = 0; jp < 8; jp++) {
                uint32_t b4[4];
                LDM4(b4, kfb + jp*16*ASTR + t*32);
                mma_f16(Sf[2*jp],   a, b4[0], b4[2]);
                mma_f16(Sf[2*jp+1], a, b4[1], b4[3]);
            }
        }
        __syncthreads();
        if (jt < iq) {                         // prefetch K(jt+1)
            attn_ld(sb + 1*ARGN, g_kf + qkbase + (size_t)(jt+1)*128*HD_, HD_, tid);
            CP_COMMIT();
        }

        // ---- scale + causal mask ----
        const int r0 = wm*16 + gr, r1 = r0 + 8;
        if (jt == iq) {
#pragma unroll
            for (int j = 0; j < 16; j++) {
                int cA = j*8 + gc, cB = cA + 1;
                Sf[j][0] = (cA > r0) ? -1e30f : Sf[j][0]*scale;
                Sf[j][1] = (cB > r0) ? -1e30f : Sf[j][1]*scale;
                Sf[j][2] = (cA > r1) ? -1e30f : Sf[j][2]*scale;
                Sf[j][3] = (cB > r1) ? -1e30f : Sf[j][3]*scale;
            }
        } else {
#pragma unroll
            for (int j = 0; j < 16; j++)
#pragma unroll
                for (int k = 0; k < 4; k++) Sf[j][k] *= scale;
        }

        // ---- online softmax ----
        float mx0 = -1e30f, mx1 = -1e30f;
#pragma unroll
        for (int j = 0; j < 16; j++) {
            mx0 = fmaxf(mx0, fmaxf(Sf[j][0], Sf[j][1]));
            mx1 = fmaxf(mx1, fmaxf(Sf[j][2], Sf[j][3]));
        }
        mx0 = fmaxf(mx0, __shfl_xor_sync(0xffffffffu, mx0, 1));
        mx0 = fmaxf(mx0, __shfl_xor_sync(0xffffffffu, mx0, 2));
        mx1 = fmaxf(mx1, __shfl_xor_sync(0xffffffffu, mx1, 1));
        mx1 = fmaxf(mx1, __shfl_xor_sync(0xffffffffu, mx1, 2));
        float mn0 = fmaxf(m0r, mx0), mn1 = fmaxf(m1r, mx1);
        float al0 = __expf(m0r - mn0), al1 = __expf(m1r - mn1);
        m0r = mn0; m1r = mn1;
        float sum0 = 0.f, sum1 = 0.f;
#pragma unroll
        for (int j = 0; j < 16; j++) {
            Sf[j][0] = __expf(Sf[j][0] - mn0); sum0 += Sf[j][0];
            Sf[j][1] = __expf(Sf[j][1] - mn0); sum0 += Sf[j][1];
            Sf[j][2] = __expf(Sf[j][2] - mn1); sum1 += Sf[j][2];
            Sf[j][3] = __expf(Sf[j][3] - mn1); sum1 += Sf[j][3];
        }
        sum0 += __shfl_xor_sync(0xffffffffu, sum0, 1);
        sum0 += __shfl_xor_sync(0xffffffffu, sum0, 2);
        sum1 += __shfl_xor_sync(0xffffffffu, sum1, 1);
        sum1 += __shfl_xor_sync(0xffffffffu, sum1, 2);
        l0r = l0r*al0 + sum0; l1r = l1r*al1 + sum1;
#pragma unroll
        for (int j = 0; j < 16; j++) {
            O[j][0] *= al0; O[j][1] *= al0;
            O[j][2] *= al1; O[j][3] *= al1;
        }

        asm volatile("cp.async.wait_group 1;" ::: "memory");
        __syncthreads();                       // V(jt) ready

        // ---- O += Ph*Vh + Pl*Vh + Ph*Vl (bf16 splits) ----
#pragma unroll
        for (int t = 0; t < 8; t++) {
            uint32_t aPh[4], aPl[4];
            aPh[0] = packbf(Sf[2*t][0],   Sf[2*t][1]);
            aPh[1] = packbf(Sf[2*t][2],   Sf[2*t][3]);
            aPh[2] = packbf(Sf[2*t+1][0], Sf[2*t+1][1]);
            aPh[3] = packbf(Sf[2*t+1][2], Sf[2*t+1][3]);
            aPl[0] = packbf(rlo(Sf[2*t][0]),   rlo(Sf[2*t][1]));
            aPl[1] = packbf(rlo(Sf[2*t][2]),   rlo(Sf[2*t][3]));
            aPl[2] = packbf(rlo(Sf[2*t+1][0]), rlo(Sf[2*t+1][1]));
            aPl[3] = packbf(rlo(Sf[2*t+1][2]), rlo(Sf[2*t+1][3]));
#pragma unroll
            for (int jp = 0; jp < 8; jp++) {
                uint32_t bh4[4], bl4[4];
                LDM4(bh4, vhb + jp*16*ASTR + t*32);
                LDM4(bl4, vlb + jp*16*ASTR + t*32);
                mma2(O[2*jp],   aPh, bh4[0], bh4[2]);
                mma2(O[2*jp+1], aPh, bh4[1], bh4[3]);
                mma2(O[2*jp],   aPl, bh4[0], bh4[2]);
                mma2(O[2*jp+1], aPl, bh4[1], bh4[3]);
                mma2(O[2*jp],   aPh, bl4[0], bl4[2]);
                mma2(O[2*jp+1], aPh, bl4[1], bl4[3]);
            }
        }
        __syncthreads();
        if (jt < iq) {                         // prefetch V(jt+1)
            attn_ld(sb + 2*ARGN, g_vth + vbase + (size_t)(jt+1)*128, S_, tid);
            attn_ld(sb + 3*ARGN, g_vtl + vbase + (size_t)(jt+1)*128, S_, tid);
            CP_COMMIT();
        }
    }

    const int b = bh >> 4, nh = bh & 15;
    float inv0 = 1.f / l0r, inv1 = 1.f / l1r;
    size_t row0 = (size_t)(b*S_ + iq*128 + wm*16 + gr);
#pragma unroll
    for (int j = 0; j < 16; j++) {
        int col = nh*HD_ + j*8 + gc;
        *(float2*)&g_attn[row0*H_ + col] =
            make_float2(O[j][0]*inv0, O[j][1]*inv0);
        *(float2*)&g_attn[(row0 + 8)*H_ + col] =
            make_float2(O[j][2]*inv1, O[j][3]*inv1);
    }
}

// ---------------- launch ----------------------------------------------------
extern "C" void kernel_launch(void* const* d_in, const int* in_sizes, int n_in,
                              void* d_out, int out_size)
{
    (void)in_sizes; (void)n_in; (void)out_size;
    const float* X  = (const float*)d_in[0];
    const float* Wq = (const float*)d_in[2];
    const float* bq = (const float*)d_in[3];
    const float* Wk = (const float*)d_in[4];
    const float* bk = (const float*)d_in[5];
    const float* Wv = (const float*)d_in[6];
    const float* bv = (const float*)d_in[7];
    const float* Wo = (const float*)d_in[8];
    const float* bo = (const float*)d_in[9];
    float* out = (float*)d_out;

    rope_table_kernel<<<(S_*64 + 255)/256, 256>>>();
    convert_f16_kernel<<<M_*H_/1024, 256>>>(X, 0);
    dim3 tb(32, 8), tg(H_/32, H_/32);
    transpose_f16_kernel<<<tg, tb>>>(Wq, 0);
    transpose_f16_kernel<<<tg, tb>>>(Wk, 1);
    transpose_f16_kernel<<<tg, tb>>>(Wv, 2);
    transpose_f16_kernel<<<tg, tb>>>(Wo, 3);

    cudaFuncSetAttribute(gemm_qk_f16, cudaFuncAttributeMaxDynamicSharedMemorySize,
                         SMEM_GF);
    gemm_qk_f16<<<dim3(32, 32), 256, SMEM_GF>>>(bq, bk);

    cudaFuncSetAttribute(gemm_v_f16, cudaFuncAttributeMaxDynamicSharedMemorySize,
                         SMEM_GF);
    gemm_v_f16<<<dim3(16, 32), 256, SMEM_GF>>>(bv);

    cudaFuncSetAttribute(attn_tc_kernel, cudaFuncAttributeMaxDynamicSharedMemorySize,
                         SMEM_AT);
    attn_tc_kernel<<<dim3(S_/128, B_*NH_), 256, SMEM_AT>>>();

    convert_f16_kernel<<<M_*H_/1024, 256>>>(nullptr, 1);
    cudaFuncSetAttribute(gemm_out_f16, cudaFuncAttributeMaxDynamicSharedMemorySize,
                         SMEM_GF);
    gemm_out_f16<<<dim3(16, 32), 256, SMEM_GF>>>(bo, out);
}

// round 9
// speedup vs baseline: 5.4702x; 1.2254x over previous
#include <cuda_runtime.h>
#include <cuda_bf16.h>
#include <cuda_fp16.h>
#include <math.h>
#include <stdint.h>

#define B_  2
#define S_  2048
#define H_  2048
#define NH_ 16
#define HD_ 128
#define M_  (B_*S_)   // 4096

// ---------------- scratch (device globals) ---------------------------------
__device__ float g_cos[S_*64];
__device__ float g_sin[S_*64];

__device__ __align__(16) __half g_Af[M_*H_];          // activations fp16
__device__ __align__(16) __half g_Bqk[2*H_*H_];       // Wq^T, Wk^T fp16
__device__ __align__(16) __half g_Bf[H_*H_];          // Wv^T fp16
__device__ __align__(16) __half g_Wf[H_*H_];          // Wo^T fp16

// attention operands
__device__ __align__(16) __half g_qf[B_*NH_*S_*HD_];  // roped Q fp16
__device__ __align__(16) __half g_kf[B_*NH_*S_*HD_];  // roped K fp16
__device__ __align__(16) __half g_vtf[B_*NH_*HD_*S_]; // V^T fp16

// ---------------- PTX helpers ----------------------------------------------
__device__ __forceinline__ uint32_t smem_u32(const void* p) {
    uint32_t a;
    asm("{ .reg .u64 t; cvta.to.shared.u64 t, %1; cvt.u32.u64 %0, t; }"
        : "=r"(a) : "l"(p));
    return a;
}
#define CP16(dst, src) \
    asm volatile("cp.async.cg.shared.global [%0], [%1], 16;" \
                 :: "r"(dst), "l"(src) : "memory")
#define CP_COMMIT() asm volatile("cp.async.commit_group;" ::: "memory")

#define LDM4(r, addr) \
    asm volatile("ldmatrix.sync.aligned.m8n8.x4.shared.b16 {%0,%1,%2,%3}, [%4];" \
        : "=r"((r)[0]), "=r"((r)[1]), "=r"((r)[2]), "=r"((r)[3]) : "r"(addr))

__device__ __forceinline__ void mma_f16(float* d, const uint32_t* a,
                                        uint32_t b0, uint32_t b1) {
    asm volatile("mma.sync.aligned.m16n8k16.row.col.f32.f16.f16.f32 "
        "{%0,%1,%2,%3}, {%4,%5,%6,%7}, {%8,%9}, {%0,%1,%2,%3};"
        : "+f"(d[0]), "+f"(d[1]), "+f"(d[2]), "+f"(d[3])
        : "r"(a[0]), "r"(a[1]), "r"(a[2]), "r"(a[3]), "r"(b0), "r"(b1));
}
__device__ __forceinline__ uint32_t packhf(float x, float y) {
    __half2 t = __floats2half2_rn(x, y);
    return *(uint32_t*)&t;
}

// ---------------- prep kernels ---------------------------------------------
__global__ void rope_table_kernel()
{
    int idx = blockIdx.x * blockDim.x + threadIdx.x;
    if (idx >= S_ * 64) return;
    int s = idx >> 6, p = idx & 63;
    double invf = exp(-log(10000.0) * (double)p / 64.0);
    double ang  = (double)s * invf;
    g_cos[idx] = (float)cos(ang);
    g_sin[idx] = (float)sin(ang);
}

// fp32 X -> fp16 g_Af
__global__ void convert_f16_kernel(const float* __restrict__ in)
{
    int i = (blockIdx.x * blockDim.x + threadIdx.x) * 4;
    float4 v = *(const float4*)&in[i];
    *(ushort4*)((unsigned short*)g_Af + i) = make_ushort4(
        __half_as_ushort(__float2half_rn(v.x)),
        __half_as_ushort(__float2half_rn(v.y)),
        __half_as_ushort(__float2half_rn(v.z)),
        __half_as_ushort(__float2half_rn(v.w)));
}

// all four W [2048,2048] -> W^T fp16 in one launch (blockIdx.z selects)
__global__ void transpose_f16_kernel(const float* __restrict__ Wq,
                                     const float* __restrict__ Wk,
                                     const float* __restrict__ Wv,
                                     const float* __restrict__ Wo)
{
    int which = blockIdx.z;
    const float* in = (which == 0) ? Wq : (which == 1) ? Wk
                    : (which == 2) ? Wv : Wo;
    __half* dst = (which < 2) ? g_Bqk + (size_t)which*H_*H_
                : (which == 2) ? g_Bf : g_Wf;
    __shared__ float t[32][33];
    int tx = threadIdx.x, ty = threadIdx.y;
    int c0 = blockIdx.x * 32, r0 = blockIdx.y * 32;
#pragma unroll
    for (int k = 0; k < 4; k++)
        t[ty + 8*k][tx] = in[(size_t)(r0 + ty + 8*k) * H_ + c0 + tx];
    __syncthreads();
#pragma unroll
    for (int k = 0; k < 4; k++)
        dst[(size_t)(c0 + ty + 8*k) * H_ + r0 + tx] =
            __float2half_rn(t[tx][ty + 8*k]);
}

// ---------------- fp16 GEMM mainloop ----------------------------------------
#define RSTR   80
#define REG_B  (128*RSTR)        // 10240
#define FSTG_B (2*REG_B)         // fp16 stage: A|B
#define SMEM_GF (4*FSTG_B)       // 81920

__device__ __forceinline__ void ld_region(uint32_t dst,
    const __half* __restrict__ src, int row0, int kb, int tid)
{
#pragma unroll
    for (int it = 0; it < 2; it++) {
        int idx = tid + it*256;
        int r = idx >> 2, c = idx & 3;
        CP16(dst + r*RSTR + c*16,
             (const void*)(src + (size_t)(row0 + r) * H_ + kb + c*8));
    }
}
__device__ __forceinline__ void ld_stage_f16(uint32_t s0,
    const __half* A, const __half* Bm, int m0, int n0, int kb, int tid)
{
    ld_region(s0,         A,  m0, kb, tid);
    ld_region(s0 + REG_B, Bm, n0, kb, tid);
    CP_COMMIT();
}

__device__ __forceinline__ void hmma_mainloop_f16(
    const __half* A, const __half* Bm,
    int m0, int n0, uint32_t sb, float acc[2][8][4])
{
    const int tid = threadIdx.x, lane = tid & 31, w = tid >> 5;
#pragma unroll
    for (int i = 0; i < 2; i++)
#pragma unroll
        for (int j = 0; j < 8; j++)
#pragma unroll
            for (int k = 0; k < 4; k++) acc[i][j][k] = 0.f;

    ld_stage_f16(sb,            A, Bm, m0, n0, 0,  tid);
    ld_stage_f16(sb +   FSTG_B, A, Bm, m0, n0, 32, tid);
    ld_stage_f16(sb + 2*FSTG_B, A, Bm, m0, n0, 64, tid);

    const int arow = (w >> 1)*32 + (lane & 15);
    const int brow = (w & 1)*32 + (lane & 15);
    const int fcol = (lane >> 4) << 4;

    for (int ch = 0; ch < 64; ch++) {
        if (ch < 62)       asm volatile("cp.async.wait_group 2;" ::: "memory");
        else if (ch == 62) asm volatile("cp.async.wait_group 1;" ::: "memory");
        else               asm volatile("cp.async.wait_group 0;" ::: "memory");
        __syncthreads();
        uint32_t s0 = sb + (ch & 3)*FSTG_B;
#pragma unroll
        for (int kk = 0; kk < 2; kk++) {
            int kB = kk*32 + fcol;
            uint32_t a[2][4], b[8][2];
#pragma unroll
            for (int mi = 0; mi < 2; mi++)
                LDM4(a[mi], s0 + (arow + mi*16)*RSTR + kB);
#pragma unroll
            for (int p = 0; p < 4; p++) {
                int r = brow + (p & 1)*16 + ((p & 2) ? 64 : 0);
                uint32_t q[4];
                LDM4(q, s0 + REG_B + r*RSTR + kB);
                b[2*p][0]   = q[0]; b[2*p][1]   = q[2];
                b[2*p+1][0] = q[1]; b[2*p+1][1] = q[3];
            }
#pragma unroll
            for (int mi = 0; mi < 2; mi++)
#pragma unroll
                for (int nj = 0; nj < 8; nj++)
                    mma_f16(acc[mi][nj], a[mi], b[nj][0], b[nj][1]);
        }
        if (ch + 3 < 64)
            ld_stage_f16(sb + ((ch + 3) & 3)*FSTG_B, A, Bm, m0, n0,
                         (ch + 3)*32, tid);
    }
}

// ---------------- Q/K projection + bias + RoPE -> fp16 ----------------------
__global__ __launch_bounds__(256, 1)
void gemm_qk_f16(const float* __restrict__ bq, const float* __restrict__ bk)
{
    extern __shared__ char dsm[];
    uint32_t sb = smem_u32(dsm);
    const int tid = threadIdx.x, lane = tid & 31, w = tid >> 5;
    const int z = blockIdx.x >> 4, nh = blockIdx.x & 15;
    const int m0 = blockIdx.y * 128, n0 = nh * 128;
    const float* bias = (z == 0) ? bq : bk;

    float acc[2][8][4];
    hmma_mainloop_f16(g_Af, g_Bqk + (size_t)z*H_*H_, m0, n0, sb, acc);

    const int gr = lane >> 2, gc = (lane & 3)*2;
    __half* oq = (z == 0) ? g_qf : g_kf;
#pragma unroll
    for (int mi = 0; mi < 2; mi++)
#pragma unroll
        for (int h = 0; h < 2; h++) {
            int m = m0 + (w >> 1)*32 + mi*16 + gr + h*8;
            int bb = m >> 11, s = m & 2047;
            size_t base = ((size_t)(bb*NH_ + nh)*S_ + s) * HD_;
#pragma unroll
            for (int nj = 0; nj < 4; nj++) {
                int c = (w & 1)*32 + nj*8 + gc;
                float vl0 = acc[mi][nj][h*2+0]   + bias[n0 + c];
                float vl1 = acc[mi][nj][h*2+1]   + bias[n0 + c + 1];
                float vh0 = acc[mi][nj+4][h*2+0] + bias[n0 + 64 + c];
                float vh1 = acc[mi][nj+4][h*2+1] + bias[n0 + 64 + c + 1];
                float cs0 = g_cos[s*64 + c],     sn0 = g_sin[s*64 + c];
                float cs1 = g_cos[s*64 + c + 1], sn1 = g_sin[s*64 + c + 1];
                *(uint32_t*)&oq[base + c] =
                    packhf(vl0*cs0 - vh0*sn0, vl1*cs1 - vh1*sn1);
                *(uint32_t*)&oq[base + 64 + c] =
                    packhf(vh0*cs0 + vl0*sn0, vh1*cs1 + vl1*sn1);
            }
        }
}

// ---------------- V projection (fp16) -> transposed fp16 --------------------
__global__ __launch_bounds__(256, 1)
void gemm_v_f16(const float* __restrict__ bv)
{
    extern __shared__ char dsm[];
    uint32_t sb = smem_u32(dsm);
    const int tid = threadIdx.x, lane = tid & 31, w = tid >> 5;
    const int nh = blockIdx.x;
    const int m0 = blockIdx.y * 128, n0 = nh * 128;

    float acc[2][8][4];
    hmma_mainloop_f16(g_Af, g_Bf, m0, n0, sb, acc);

    const int gr = lane >> 2, gc = (lane & 3)*2;
#pragma unroll
    for (int mi = 0; mi < 2; mi++)
#pragma unroll
        for (int h = 0; h < 2; h++) {
            int m = m0 + (w >> 1)*32 + mi*16 + gr + h*8;
            int bb = m >> 11, s = m & 2047;
            size_t vb = (size_t)(bb*NH_ + nh) * HD_;
#pragma unroll
            for (int nj = 0; nj < 4; nj++) {
                int c = (w & 1)*32 + nj*8 + gc;
                float vv[4] = {acc[mi][nj][h*2+0]   + bv[n0 + c],
                               acc[mi][nj][h*2+1]   + bv[n0 + c + 1],
                               acc[mi][nj+4][h*2+0] + bv[n0 + 64 + c],
                               acc[mi][nj+4][h*2+1] + bv[n0 + 64 + c + 1]};
                int   cc[4] = {c, c + 1, 64 + c, 64 + c + 1};
#pragma unroll
                for (int u = 0; u < 4; u++)
                    g_vtf[(vb + cc[u])*S_ + s] = __float2half_rn(vv[u]);
            }
        }
}

// ---------------- output projection (fp16) ----------------------------------
__global__ __launch_bounds__(256, 1)
void gemm_out_f16(const float* __restrict__ bo, float* __restrict__ out)
{
    extern __shared__ char dsm[];
    uint32_t sb = smem_u32(dsm);
    const int tid = threadIdx.x, lane = tid & 31, w = tid >> 5;
    const int m0 = blockIdx.y * 128, n0 = blockIdx.x * 128;

    float acc[2][8][4];
    hmma_mainloop_f16(g_Af, g_Wf, m0, n0, sb, acc);

    const int gr = lane >> 2, gc = (lane & 3)*2;
#pragma unroll
    for (int mi = 0; mi < 2; mi++)
#pragma unroll
        for (int h = 0; h < 2; h++) {
            int m = m0 + (w >> 1)*32 + mi*16 + gr + h*8;
            float* op = out + (size_t)m * H_ + n0;
#pragma unroll
            for (int nj = 0; nj < 4; nj++) {
                int c = (w & 1)*32 + nj*8 + gc;
                *(float2*)&op[c] = make_float2(
                    acc[mi][nj][h*2+0] + bo[n0 + c],
                    acc[mi][nj][h*2+1] + bo[n0 + c + 1]);
                *(float2*)&op[64 + c] = make_float2(
                    acc[mi][nj+4][h*2+0] + bo[n0 + 64 + c],
                    acc[mi][nj+4][h*2+1] + bo[n0 + 64 + c + 1]);
            }
        }
}

// ---------------- tensor-core causal flash attention (all fp16) -------------
// regions: 0 Qf 1 Kf 2 Vf
#define ASTR 272
#define ARGN (128*ASTR)
#define SMEM_AT (3*ARGN)         // 104448

__device__ __forceinline__ void attn_ld(uint32_t dst,
    const __half* __restrict__ src, int stride, int tid)
{
#pragma unroll
    for (int it = 0; it < 8; it++) {
        int idx = tid + it*256;
        int r = idx >> 4, c = idx & 15;
        CP16(dst + r*ASTR + c*16, (const void*)(src + (size_t)r*stride + c*8));
    }
}

__global__ __launch_bounds__(256, 1)
void attn_tc_kernel()
{
    extern __shared__ char dsm[];
    uint32_t sb = smem_u32(dsm);
    const int tid = threadIdx.x, lane = tid & 31, wm = tid >> 5;
    const int gr = lane >> 2, gc = (lane & 3)*2;
    const int bh = blockIdx.y;
    const int iq = (int)gridDim.x - 1 - (int)blockIdx.x;
    const int laneoff = (lane & 15)*ASTR + (lane >> 4)*16;
    const float scale = 0.08838834764831845f;

    const size_t qkbase = (size_t)bh * S_ * HD_;
    const size_t vbase  = (size_t)bh * HD_ * S_;

    attn_ld(sb + 0*ARGN, g_qf + qkbase + (size_t)iq*128*HD_, HD_, tid);
    CP_COMMIT();
    attn_ld(sb + 1*ARGN, g_kf + qkbase, HD_, tid);
    CP_COMMIT();
    attn_ld(sb + 2*ARGN, g_vtf + vbase, S_, tid);
    CP_COMMIT();

    const uint32_t qfb = sb + 0*ARGN + wm*16*ASTR + laneoff;
    const uint32_t kfb = sb + 1*ARGN + laneoff;
    const uint32_t vfb = sb + 2*ARGN + laneoff;

    float O[16][4];
#pragma unroll
    for (int j = 0; j < 16; j++)
#pragma unroll
        for (int k = 0; k < 4; k++) O[j][k] = 0.f;
    float m0r = -1e30f, m1r = -1e30f, l0r = 0.f, l1r = 0.f;

    for (int jt = 0; jt <= iq; jt++) {
        asm volatile("cp.async.wait_group 1;" ::: "memory");
        __syncthreads();                       // Q + K(jt) ready

        // ---- S = Q K^T (fp16) ----
        float Sf[16][4];
#pragma unroll
        for (int j = 0; j < 16; j++)
#pragma unroll
            for (int k = 0; k < 4; k++) Sf[j][k] = 0.f;
#pragma unroll
        for (int t = 0; t < 8; t++) {
            uint32_t a[4];
            LDM4(a, qfb + t*32);
#pragma unroll
            for (int jp = 0; jp < 8; jp++) {
                uint32_t b4[4];
                LDM4(b4, kfb + jp*16*ASTR + t*32);
                mma_f16(Sf[2*jp],   a, b4[0], b4[2]);
                mma_f16(Sf[2*jp+1], a, b4[1], b4[3]);
            }
        }
        __syncthreads();
        if (jt < iq) {                         // prefetch K(jt+1)
            attn_ld(sb + 1*ARGN, g_kf + qkbase + (size_t)(jt+1)*128*HD_, HD_, tid);
            CP_COMMIT();
        }

        // ---- scale + causal mask ----
        const int r0 = wm*16 + gr, r1 = r0 + 8;
        if (jt == iq) {
#pragma unroll
            for (int j = 0; j < 16; j++) {
                int cA = j*8 + gc, cB = cA + 1;
                Sf[j][0] = (cA > r0) ? -1e30f : Sf[j][0]*scale;
                Sf[j][1] = (cB > r0) ? -1e30f : Sf[j][1]*scale;
                Sf[j][2] = (cA > r1) ? -1e30f : Sf[j][2]*scale;
                Sf[j][3] = (cB > r1) ? -1e30f : Sf[j][3]*scale;
            }
        } else {
#pragma unroll
            for (int j = 0; j < 16; j++)
#pragma unroll
                for (int k = 0; k < 4; k++) Sf[j][k] *= scale;
        }

        // ---- online softmax ----
        float mx0 = -1e30f, mx1 = -1e30f;
#pragma unroll
        for (int j = 0; j < 16; j++) {
            mx0 = fmaxf(mx0, fmaxf(Sf[j][0], Sf[j][1]));
            mx1 = fmaxf(mx1, fmaxf(Sf[j][2], Sf[j][3]));
        }
        mx0 = fmaxf(mx0, __shfl_xor_sync(0xffffffffu, mx0, 1));
        mx0 = fmaxf(mx0, __shfl_xor_sync(0xffffffffu, mx0, 2));
        mx1 = fmaxf(mx1, __shfl_xor_sync(0xffffffffu, mx1, 1));
        mx1 = fmaxf(mx1, __shfl_xor_sync(0xffffffffu, mx1, 2));
        float mn0 = fmaxf(m0r, mx0), mn1 = fmaxf(m1r, mx1);
        float al0 = __expf(m0r - mn0), al1 = __expf(m1r - mn1);
        m0r = mn0; m1r = mn1;
        float sum0 = 0.f, sum1 = 0.f;
#pragma unroll
        for (int j = 0; j < 16; j++) {
            Sf[j][0] = __expf(Sf[j][0] - mn0); sum0 += Sf[j][0];
            Sf[j][1] = __expf(Sf[j][1] - mn0); sum0 += Sf[j][1];
            Sf[j][2] = __expf(Sf[j][2] - mn1); sum1 += Sf[j][2];
            Sf[j][3] = __expf(Sf[j][3] - mn1); sum1 += Sf[j][3];
        }
        sum0 += __shfl_xor_sync(0xffffffffu, sum0, 1);
        sum0 += __shfl_xor_sync(0xffffffffu, sum0, 2);
        sum1 += __shfl_xor_sync(0xffffffffu, sum1, 1);
        sum1 += __shfl_xor_sync(0xffffffffu, sum1, 2);
        l0r = l0r*al0 + sum0; l1r = l1r*al1 + sum1;
#pragma unroll
        for (int j = 0; j < 16; j++) {
            O[j][0] *= al0; O[j][1] *= al0;
            O[j][2] *= al1; O[j][3] *= al1;
        }

        asm volatile("cp.async.wait_group 1;" ::: "memory");
        __syncthreads();                       // V(jt) ready

        // ---- O += P V (fp16) ----
#pragma unroll
        for (int t = 0; t < 8; t++) {
            uint32_t aP[4];
            aP[0] = packhf(Sf[2*t][0],   Sf[2*t][1]);
            aP[1] = packhf(Sf[2*t][2],   Sf[2*t][3]);
            aP[2] = packhf(Sf[2*t+1][0], Sf[2*t+1][1]);
            aP[3] = packhf(Sf[2*t+1][2], Sf[2*t+1][3]);
#pragma unroll
            for (int jp = 0; jp < 8; jp++) {
                uint32_t b4[4];
                LDM4(b4, vfb + jp*16*ASTR + t*32);
                mma_f16(O[2*jp],   aP, b4[0], b4[2]);
                mma_f16(O[2*jp+1], aP, b4[1], b4[3]);
            }
        }
        __syncthreads();
        if (jt < iq) {                         // prefetch V(jt+1)
            attn_ld(sb + 2*ARGN, g_vtf + vbase + (size_t)(jt+1)*128, S_, tid);
            CP_COMMIT();
        }
    }

    // ---- finalize: write fp16 g_Af directly (identical rounding to the
    //      old fp32-store + convert kernel, with half the traffic) ----
    const int b = bh >> 4, nh = bh & 15;
    float inv0 = 1.f / l0r, inv1 = 1.f / l1r;
    size_t row0 = (size_t)(b*S_ + iq*128 + wm*16 + gr);
#pragma unroll
    for (int j = 0; j < 16; j++) {
        int col = nh*HD_ + j*8 + gc;
        *(uint32_t*)&g_Af[row0*H_ + col] =
            packhf(O[j][0]*inv0, O[j][1]*inv0);
        *(uint32_t*)&g_Af[(row0 + 8)*H_ + col] =
            packhf(O[j][2]*inv1, O[j][3]*inv1);
    }
}

// ---------------- launch ----------------------------------------------------
extern "C" void kernel_launch(void* const* d_in, const int* in_sizes, int n_in,
                              void* d_out, int out_size)
{
    (void)in_sizes; (void)n_in; (void)out_size;
    const float* X  = (const float*)d_in[0];
    const float* Wq = (const float*)d_in[2];
    const float* bq = (const float*)d_in[3];
    const float* Wk = (const float*)d_in[4];
    const float* bk = (const float*)d_in[5];
    const float* Wv = (const float*)d_in[6];
    const float* bv = (const float*)d_in[7];
    const float* Wo = (const float*)d_in[8];
    const float* bo = (const float*)d_in[9];
    float* out = (float*)d_out;

    rope_table_kernel<<<(S_*64 + 255)/256, 256>>>();
    convert_f16_kernel<<<M_*H_/1024, 256>>>(X);
    transpose_f16_kernel<<<dim3(H_/32, H_/32, 4), dim3(32, 8)>>>(Wq, Wk, Wv, Wo);

    cudaFuncSetAttribute(gemm_qk_f16, cudaFuncAttributeMaxDynamicSharedMemorySize,
                         SMEM_GF);
    gemm_qk_f16<<<dim3(32, 32), 256, SMEM_GF>>>(bq, bk);

    cudaFuncSetAttribute(gemm_v_f16, cudaFuncAttributeMaxDynamicSharedMemorySize,
                         SMEM_GF);
    gemm_v_f16<<<dim3(16, 32), 256, SMEM_GF>>>(bv);

    cudaFuncSetAttribute(attn_tc_kernel, cudaFuncAttributeMaxDynamicSharedMemorySize,
                         SMEM_AT);
    attn_tc_kernel<<<dim3(S_/128, B_*NH_), 256, SMEM_AT>>>();

    cudaFuncSetAttribute(gemm_out_f16, cudaFuncAttributeMaxDynamicSharedMemorySize,
                         SMEM_GF);
    gemm_out_f16<<<dim3(16, 32), 256, SMEM_GF>>>(bo, out);
}

// round 10
// speedup vs baseline: 6.2157x; 1.1363x over previous
#include <cuda_runtime.h>
#include <cuda_bf16.h>
#include <cuda_fp16.h>
#include <math.h>
#include <stdint.h>

#define B_  2
#define S_  2048
#define H_  2048
#define NH_ 16
#define HD_ 128
#define M_  (B_*S_)   // 4096

// ---------------- scratch (device globals) ---------------------------------
__device__ float g_cos[S_*64];
__device__ float g_sin[S_*64];

__device__ __align__(16) __half g_Af[M_*H_];          // activations fp16
__device__ __align__(16) __half g_Bqk[2*H_*H_];       // Wq^T, Wk^T fp16
__device__ __align__(16) __half g_Bf[H_*H_];          // Wv^T fp16
__device__ __align__(16) __half g_Wf[H_*H_];          // Wo^T fp16

// attention operands
__device__ __align__(16) __half g_qf[B_*NH_*S_*HD_];  // roped Q fp16
__device__ __align__(16) __half g_kf[B_*NH_*S_*HD_];  // roped K fp16
__device__ __align__(16) __half g_vtf[B_*NH_*HD_*S_]; // V^T fp16

// ---------------- PTX helpers ----------------------------------------------
__device__ __forceinline__ uint32_t smem_u32(const void* p) {
    uint32_t a;
    asm("{ .reg .u64 t; cvta.to.shared.u64 t, %1; cvt.u32.u64 %0, t; }"
        : "=r"(a) : "l"(p));
    return a;
}
#define CP16(dst, src) \
    asm volatile("cp.async.cg.shared.global [%0], [%1], 16;" \
                 :: "r"(dst), "l"(src) : "memory")
#define CP_COMMIT() asm volatile("cp.async.commit_group;" ::: "memory")

#define LDM4(r, addr) \
    asm volatile("ldmatrix.sync.aligned.m8n8.x4.shared.b16 {%0,%1,%2,%3}, [%4];" \
        : "=r"((r)[0]), "=r"((r)[1]), "=r"((r)[2]), "=r"((r)[3]) : "r"(addr))

__device__ __forceinline__ void mma_f16(float* d, const uint32_t* a,
                                        uint32_t b0, uint32_t b1) {
    asm volatile("mma.sync.aligned.m16n8k16.row.col.f32.f16.f16.f32 "
        "{%0,%1,%2,%3}, {%4,%5,%6,%7}, {%8,%9}, {%0,%1,%2,%3};"
        : "+f"(d[0]), "+f"(d[1]), "+f"(d[2]), "+f"(d[3])
        : "r"(a[0]), "r"(a[1]), "r"(a[2]), "r"(a[3]), "r"(b0), "r"(b1));
}
__device__ __forceinline__ uint32_t packhf(float x, float y) {
    __half2 t = __floats2half2_rn(x, y);
    return *(uint32_t*)&t;
}

// ---------------- prep kernels ---------------------------------------------
__global__ void rope_table_kernel()
{
    int idx = blockIdx.x * blockDim.x + threadIdx.x;
    if (idx >= S_ * 64) return;
    int s = idx >> 6, p = idx & 63;
    double invf = exp(-log(10000.0) * (double)p / 64.0);
    double ang  = (double)s * invf;
    g_cos[idx] = (float)cos(ang);
    g_sin[idx] = (float)sin(ang);
}

// fp32 X -> fp16 g_Af
__global__ void convert_f16_kernel(const float* __restrict__ in)
{
    int i = (blockIdx.x * blockDim.x + threadIdx.x) * 4;
    float4 v = *(const float4*)&in[i];
    *(ushort4*)((unsigned short*)g_Af + i) = make_ushort4(
        __half_as_ushort(__float2half_rn(v.x)),
        __half_as_ushort(__float2half_rn(v.y)),
        __half_as_ushort(__float2half_rn(v.z)),
        __half_as_ushort(__float2half_rn(v.w)));
}

// all four W [2048,2048] -> W^T fp16 in one launch (blockIdx.z selects)
__global__ void transpose_f16_kernel(const float* __restrict__ Wq,
                                     const float* __restrict__ Wk,
                                     const float* __restrict__ Wv,
                                     const float* __restrict__ Wo)
{
    int which = blockIdx.z;
    const float* in = (which == 0) ? Wq : (which == 1) ? Wk
                    : (which == 2) ? Wv : Wo;
    __half* dst = (which < 2) ? g_Bqk + (size_t)which*H_*H_
                : (which == 2) ? g_Bf : g_Wf;
    __shared__ float t[32][33];
    int tx = threadIdx.x, ty = threadIdx.y;
    int c0 = blockIdx.x * 32, r0 = blockIdx.y * 32;
#pragma unroll
    for (int k = 0; k < 4; k++)
        t[ty + 8*k][tx] = in[(size_t)(r0 + ty + 8*k) * H_ + c0 + tx];
    __syncthreads();
#pragma unroll
    for (int k = 0; k < 4; k++)
        dst[(size_t)(c0 + ty + 8*k) * H_ + r0 + tx] =
            __float2half_rn(t[tx][ty + 8*k]);
}

// ---------------- fp16 GEMM mainloop ----------------------------------------
// 64B swizzled rows: phys = r*64 + 16*(g ^ ((r>>1)&3)), g = 16B granule 0..3.
// Conflict-free for cp.async 16B writes and ldmatrix x4 reads.
// 6 stages, one barrier per TWO 32-K chunks.
#define REG_B  8192              // 128 rows x 64B
#define FSTG_B (2*REG_B)         // A|B regions = 16384
#define SMEM_GF (6*FSTG_B)       // 98304

__device__ __forceinline__ void ld_region(uint32_t dst,
    const __half* __restrict__ src, int row0, int kb, int tid)
{
#pragma unroll
    for (int it = 0; it < 2; it++) {
        int idx = tid + it*256;           // 512 granules
        int r = idx >> 2, g = idx & 3;
        uint32_t sw = (uint32_t)((g ^ ((r >> 1) & 3)) << 4);
        CP16(dst + r*64 + sw,
             (const void*)(src + (size_t)(row0 + r) * H_ + kb + g*8));
    }
}
__device__ __forceinline__ void ld_stage_f16(uint32_t s0,
    const __half* A, const __half* Bm, int m0, int n0, int kb, int tid)
{
    ld_region(s0,         A,  m0, kb, tid);
    ld_region(s0 + REG_B, Bm, n0, kb, tid);
    CP_COMMIT();
}

__device__ __forceinline__ void hmma_mainloop_f16(
    const __half* A, const __half* Bm,
    int m0, int n0, uint32_t sb, float acc[2][8][4])
{
    const int tid = threadIdx.x, lane = tid & 31, w = tid >> 5;
#pragma unroll
    for (int i = 0; i < 2; i++)
#pragma unroll
        for (int j = 0; j < 8; j++)
#pragma unroll
            for (int k = 0; k < 4; k++) acc[i][j][k] = 0.f;

    // prologue: chunks 0..3 into slots 0..3
    ld_stage_f16(sb + 0*FSTG_B, A, Bm, m0, n0, 0,  tid);
    ld_stage_f16(sb + 1*FSTG_B, A, Bm, m0, n0, 32, tid);
    ld_stage_f16(sb + 2*FSTG_B, A, Bm, m0, n0, 64, tid);
    ld_stage_f16(sb + 3*FSTG_B, A, Bm, m0, n0, 96, tid);

    // per-thread fragment addressing (swizzled)
    const int hi  = lane >> 4;            // 16B column select
    const int rsw = (lane >> 1) & 3;      // swizzle const (same for all rows)
    const uint32_t swz0 = (uint32_t)(((0 + hi) ^ rsw) << 4);   // kk=0
    const uint32_t swz1 = (uint32_t)(((2 + hi) ^ rsw) << 4);   // kk=1
    const uint32_t arow64 = (uint32_t)(((w >> 1)*32 + (lane & 15)) * 64);
    const uint32_t brow64 = (uint32_t)(((w & 1)*32 + (lane & 15)) * 64);

    for (int i = 0; i < 32; i++) {
        const int cA = 2*i;
        if (i < 31) asm volatile("cp.async.wait_group 2;" ::: "memory");
        else        asm volatile("cp.async.wait_group 0;" ::: "memory");
        __syncthreads();
        // post-barrier loads: slots of chunks cA-2, cA-1 (finished last iter)
        if (cA + 4 < 64) {
            ld_stage_f16(sb + ((cA+4)%6)*FSTG_B, A, Bm, m0, n0, (cA+4)*32, tid);
            ld_stage_f16(sb + ((cA+5)%6)*FSTG_B, A, Bm, m0, n0, (cA+5)*32, tid);
        }
#pragma unroll
        for (int cc = 0; cc < 2; cc++) {
            uint32_t s0 = sb + (uint32_t)(((cA + cc) % 6) * FSTG_B);
#pragma unroll
            for (int kk = 0; kk < 2; kk++) {
                uint32_t swz = kk ? swz1 : swz0;
                uint32_t a[2][4], b[8][2];
                LDM4(a[0], s0 + arow64 + swz);
                LDM4(a[1], s0 + arow64 + 1024 + swz);
#pragma unroll
                for (int p = 0; p < 4; p++) {
                    uint32_t roff = (uint32_t)(((p & 1)*16 + ((p & 2) ? 64 : 0)) * 64);
                    uint32_t q[4];
                    LDM4(q, s0 + REG_B + brow64 + roff + swz);
                    b[2*p][0]   = q[0]; b[2*p][1]   = q[2];
                    b[2*p+1][0] = q[1]; b[2*p+1][1] = q[3];
                }
#pragma unroll
                for (int mi = 0; mi < 2; mi++)
#pragma unroll
                    for (int nj = 0; nj < 8; nj++)
                        mma_f16(acc[mi][nj], a[mi], b[nj][0], b[nj][1]);
            }
        }
    }
}

// ---------------- QKV projection + bias (+RoPE) -> fp16 ---------------------
// grid (48, 32): z = x>>4 (0=q,1=k,2=v), nh = x&15 ; y -> m-tile
__global__ __launch_bounds__(256, 2)
void gemm_qkv_f16(const float* __restrict__ bq, const float* __restrict__ bk,
                  const float* __restrict__ bv)
{
    extern __shared__ char dsm[];
    uint32_t sb = smem_u32(dsm);
    const int tid = threadIdx.x, lane = tid & 31, w = tid >> 5;
    const int z = blockIdx.x >> 4, nh = blockIdx.x & 15;
    const int m0 = blockIdx.y * 128, n0 = nh * 128;
    const float* bias = (z == 0) ? bq : (z == 1) ? bk : bv;
    const __half* Bm  = (z < 2) ? g_Bqk + (size_t)z*H_*H_ : g_Bf;

    float acc[2][8][4];
    hmma_mainloop_f16(g_Af, Bm, m0, n0, sb, acc);

    const int gr = lane >> 2, gc = (lane & 3)*2;
    if (z < 2) {
        __half* oq = (z == 0) ? g_qf : g_kf;
#pragma unroll
        for (int mi = 0; mi < 2; mi++)
#pragma unroll
            for (int h = 0; h < 2; h++) {
                int m = m0 + (w >> 1)*32 + mi*16 + gr + h*8;
                int bb = m >> 11, s = m & 2047;
                size_t base = ((size_t)(bb*NH_ + nh)*S_ + s) * HD_;
#pragma unroll
                for (int nj = 0; nj < 4; nj++) {
                    int c = (w & 1)*32 + nj*8 + gc;
                    float vl0 = acc[mi][nj][h*2+0]   + bias[n0 + c];
                    float vl1 = acc[mi][nj][h*2+1]   + bias[n0 + c + 1];
                    float vh0 = acc[mi][nj+4][h*2+0] + bias[n0 + 64 + c];
                    float vh1 = acc[mi][nj+4][h*2+1] + bias[n0 + 64 + c + 1];
                    float cs0 = g_cos[s*64 + c],     sn0 = g_sin[s*64 + c];
                    float cs1 = g_cos[s*64 + c + 1], sn1 = g_sin[s*64 + c + 1];
                    *(uint32_t*)&oq[base + c] =
                        packhf(vl0*cs0 - vh0*sn0, vl1*cs1 - vh1*sn1);
                    *(uint32_t*)&oq[base + 64 + c] =
                        packhf(vh0*cs0 + vl0*sn0, vh1*cs1 + vl1*sn1);
                }
            }
    } else {
#pragma unroll
        for (int mi = 0; mi < 2; mi++)
#pragma unroll
            for (int h = 0; h < 2; h++) {
                int m = m0 + (w >> 1)*32 + mi*16 + gr + h*8;
                int bb = m >> 11, s = m & 2047;
                size_t vb = (size_t)(bb*NH_ + nh) * HD_;
#pragma unroll
                for (int nj = 0; nj < 4; nj++) {
                    int c = (w & 1)*32 + nj*8 + gc;
                    float vv[4] = {acc[mi][nj][h*2+0]   + bias[n0 + c],
                                   acc[mi][nj][h*2+1]   + bias[n0 + c + 1],
                                   acc[mi][nj+4][h*2+0] + bias[n0 + 64 + c],
                                   acc[mi][nj+4][h*2+1] + bias[n0 + 64 + c + 1]};
                    int   cc[4] = {c, c + 1, 64 + c, 64 + c + 1};
#pragma unroll
                    for (int u = 0; u < 4; u++)
                        g_vtf[(vb + cc[u])*S_ + s] = __float2half_rn(vv[u]);
                }
            }
    }
}

// ---------------- output projection (fp16) ----------------------------------
__global__ __launch_bounds__(256, 2)
void gemm_out_f16(const float* __restrict__ bo, float* __restrict__ out)
{
    extern __shared__ char dsm[];
    uint32_t sb = smem_u32(dsm);
    const int tid = threadIdx.x, lane = tid & 31, w = tid >> 5;
    const int m0 = blockIdx.y * 128, n0 = blockIdx.x * 128;

    float acc[2][8][4];
    hmma_mainloop_f16(g_Af, g_Wf, m0, n0, sb, acc);

    const int gr = lane >> 2, gc = (lane & 3)*2;
#pragma unroll
    for (int mi = 0; mi < 2; mi++)
#pragma unroll
        for (int h = 0; h < 2; h++) {
            int m = m0 + (w >> 1)*32 + mi*16 + gr + h*8;
            float* op = out + (size_t)m * H_ + n0;
#pragma unroll
            for (int nj = 0; nj < 4; nj++) {
                int c = (w & 1)*32 + nj*8 + gc;
                *(float2*)&op[c] = make_float2(
                    acc[mi][nj][h*2+0] + bo[n0 + c],
                    acc[mi][nj][h*2+1] + bo[n0 + c + 1]);
                *(float2*)&op[64 + c] = make_float2(
                    acc[mi][nj+4][h*2+0] + bo[n0 + 64 + c],
                    acc[mi][nj+4][h*2+1] + bo[n0 + 64 + c + 1]);
            }
        }
}

// ---------------- tensor-core causal flash attention (all fp16) -------------
// regions: 0 Qf 1 Kf 2 Vf
#define ASTR 272
#define ARGN (128*ASTR)
#define SMEM_AT (3*ARGN)         // 104448

__device__ __forceinline__ void attn_ld(uint32_t dst,
    const __half* __restrict__ src, int stride, int tid)
{
#pragma unroll
    for (int it = 0; it < 8; it++) {
        int idx = tid + it*256;
        int r = idx >> 4, c = idx & 15;
        CP16(dst + r*ASTR + c*16, (const void*)(src + (size_t)r*stride + c*8));
    }
}

__global__ __launch_bounds__(256, 1)
void attn_tc_kernel()
{
    extern __shared__ char dsm[];
    uint32_t sb = smem_u32(dsm);
    const int tid = threadIdx.x, lane = tid & 31, wm = tid >> 5;
    const int gr = lane >> 2, gc = (lane & 3)*2;
    const int bh = blockIdx.y;
    const int iq = (int)gridDim.x - 1 - (int)blockIdx.x;
    const int laneoff = (lane & 15)*ASTR + (lane >> 4)*16;
    const float scale = 0.08838834764831845f;

    const size_t qkbase = (size_t)bh * S_ * HD_;
    const size_t vbase  = (size_t)bh * HD_ * S_;

    attn_ld(sb + 0*ARGN, g_qf + qkbase + (size_t)iq*128*HD_, HD_, tid);
    CP_COMMIT();
    attn_ld(sb + 1*ARGN, g_kf + qkbase, HD_, tid);
    CP_COMMIT();
    attn_ld(sb + 2*ARGN, g_vtf + vbase, S_, tid);
    CP_COMMIT();

    const uint32_t qfb = sb + 0*ARGN + wm*16*ASTR + laneoff;
    const uint32_t kfb = sb + 1*ARGN + laneoff;
    const uint32_t vfb = sb + 2*ARGN + laneoff;

    float O[16][4];
#pragma unroll
    for (int j = 0; j < 16; j++)
#pragma unroll
        for (int k = 0; k < 4; k++) O[j][k] = 0.f;
    float m0r = -1e30f, m1r = -1e30f, l0r = 0.f, l1r = 0.f;

    for (int jt = 0; jt <= iq; jt++) {
        asm volatile("cp.async.wait_group 1;" ::: "memory");
        __syncthreads();                       // Q + K(jt) ready

        // ---- S = Q K^T (fp16) ----
        float Sf[16][4];
#pragma unroll
        for (int j = 0; j < 16; j++)
#pragma unroll
            for (int k = 0; k < 4; k++) Sf[j][k] = 0.f;
#pragma unroll
        for (int t = 0; t < 8; t++) {
            uint32_t a[4];
            LDM4(a, qfb + t*32);
#pragma unroll
            for (int jp = 0; jp < 8; jp++) {
                uint32_t b4[4];
                LDM4(b4, kfb + jp*16*ASTR + t*32);
                mma_f16(Sf[2*jp],   a, b4[0], b4[2]);
                mma_f16(Sf[2*jp+1], a, b4[1], b4[3]);
            }
        }
        __syncthreads();
        if (jt < iq) {                         // prefetch K(jt+1)
            attn_ld(sb + 1*ARGN, g_kf + qkbase + (size_t)(jt+1)*128*HD_, HD_, tid);
            CP_COMMIT();
        }

        // ---- scale + causal mask ----
        const int r0 = wm*16 + gr, r1 = r0 + 8;
        if (jt == iq) {
#pragma unroll
            for (int j = 0; j < 16; j++) {
                int cA = j*8 + gc, cB = cA + 1;
                Sf[j][0] = (cA > r0) ? -1e30f : Sf[j][0]*scale;
                Sf[j][1] = (cB > r0) ? -1e30f : Sf[j][1]*scale;
                Sf[j][2] = (cA > r1) ? -1e30f : Sf[j][2]*scale;
                Sf[j][3] = (cB > r1) ? -1e30f : Sf[j][3]*scale;
            }
        } else {
#pragma unroll
            for (int j = 0; j < 16; j++)
#pragma unroll
                for (int k = 0; k < 4; k++) Sf[j][k] *= scale;
        }

        // ---- online softmax ----
        float mx0 = -1e30f, mx1 = -1e30f;
#pragma unroll
        for (int j = 0; j < 16; j++) {
            mx0 = fmaxf(mx0, fmaxf(Sf[j][0], Sf[j][1]));
            mx1 = fmaxf(mx1, fmaxf(Sf[j][2], Sf[j][3]));
        }
        mx0 = fmaxf(mx0, __shfl_xor_sync(0xffffffffu, mx0, 1));
        mx0 = fmaxf(mx0, __shfl_xor_sync(0xffffffffu, mx0, 2));
        mx1 = fmaxf(mx1, __shfl_xor_sync(0xffffffffu, mx1, 1));
        mx1 = fmaxf(mx1, __shfl_xor_sync(0xffffffffu, mx1, 2));
        float mn0 = fmaxf(m0r, mx0), mn1 = fmaxf(m1r, mx1);
        float al0 = __expf(m0r - mn0), al1 = __expf(m1r - mn1);
        m0r = mn0; m1r = mn1;
        float sum0 = 0.f, sum1 = 0.f;
#pragma unroll
        for (int j = 0; j < 16; j++) {
            Sf[j][0] = __expf(Sf[j][0] - mn0); sum0 += Sf[j][0];
            Sf[j][1] = __expf(Sf[j][1] - mn0); sum0 += Sf[j][1];
            Sf[j][2] = __expf(Sf[j][2] - mn1); sum1 += Sf[j][2];
            Sf[j][3] = __expf(Sf[j][3] - mn1); sum1 += Sf[j][3];
        }
        sum0 += __shfl_xor_sync(0xffffffffu, sum0, 1);
        sum0 += __shfl_xor_sync(0xffffffffu, sum0, 2);
        sum1 += __shfl_xor_sync(0xffffffffu, sum1, 1);
        sum1 += __shfl_xor_sync(0xffffffffu, sum1, 2);
        l0r = l0r*al0 + sum0; l1r = l1r*al1 + sum1;
#pragma unroll
        for (int j = 0; j < 16; j++) {
            O[j][0] *= al0; O[j][1] *= al0;
            O[j][2] *= al1; O[j][3] *= al1;
        }

        asm volatile("cp.async.wait_group 1;" ::: "memory");
        __syncthreads();                       // V(jt) ready

        // ---- O += P V (fp16) ----
#pragma unroll
        for (int t = 0; t < 8; t++) {
            uint32_t aP[4];
            aP[0] = packhf(Sf[2*t][0],   Sf[2*t][1]);
            aP[1] = packhf(Sf[2*t][2],   Sf[2*t][3]);
            aP[2] = packhf(Sf[2*t+1][0], Sf[2*t+1][1]);
            aP[3] = packhf(Sf[2*t+1][2], Sf[2*t+1][3]);
#pragma unroll
            for (int jp = 0; jp < 8; jp++) {
                uint32_t b4[4];
                LDM4(b4, vfb + jp*16*ASTR + t*32);
                mma_f16(O[2*jp],   aP, b4[0], b4[2]);
                mma_f16(O[2*jp+1], aP, b4[1], b4[3]);
            }
        }
        __syncthreads();
        if (jt < iq) {                         // prefetch V(jt+1)
            attn_ld(sb + 2*ARGN, g_vtf + vbase + (size_t)(jt+1)*128, S_, tid);
            CP_COMMIT();
        }
    }

    // ---- finalize: write fp16 g_Af directly ----
    const int b = bh >> 4, nh = bh & 15;
    float inv0 = 1.f / l0r, inv1 = 1.f / l1r;
    size_t row0 = (size_t)(b*S_ + iq*128 + wm*16 + gr);
#pragma unroll
    for (int j = 0; j < 16; j++) {
        int col = nh*HD_ + j*8 + gc;
        *(uint32_t*)&g_Af[row0*H_ + col] =
            packhf(O[j][0]*inv0, O[j][1]*inv0);
        *(uint32_t*)&g_Af[(row0 + 8)*H_ + col] =
            packhf(O[j][2]*inv1, O[j][3]*inv1);
    }
}

// ---------------- launch ----------------------------------------------------
extern "C" void kernel_launch(void* const* d_in, const int* in_sizes, int n_in,
                              void* d_out, int out_size)
{
    (void)in_sizes; (void)n_in; (void)out_size;
    const float* X  = (const float*)d_in[0];
    const float* Wq = (const float*)d_in[2];
    const float* bq = (const float*)d_in[3];
    const float* Wk = (const float*)d_in[4];
    const float* bk = (const float*)d_in[5];
    const float* Wv = (const float*)d_in[6];
    const float* bv = (const float*)d_in[7];
    const float* Wo = (const float*)d_in[8];
    const float* bo = (const float*)d_in[9];
    float* out = (float*)d_out;

    rope_table_kernel<<<(S_*64 + 255)/256, 256>>>();
    convert_f16_kernel<<<M_*H_/1024, 256>>>(X);
    transpose_f16_kernel<<<dim3(H_/32, H_/32, 4), dim3(32, 8)>>>(Wq, Wk, Wv, Wo);

    cudaFuncSetAttribute(gemm_qkv_f16, cudaFuncAttributeMaxDynamicSharedMemorySize,
                         SMEM_GF);
    gemm_qkv_f16<<<dim3(48, 32), 256, SMEM_GF>>>(bq, bk, bv);

    cudaFuncSetAttribute(attn_tc_kernel, cudaFuncAttributeMaxDynamicSharedMemorySize,
                         SMEM_AT);
    attn_tc_kernel<<<dim3(S_/128, B_*NH_), 256, SMEM_AT>>>();

    cudaFuncSetAttribute(gemm_out_f16, cudaFuncAttributeMaxDynamicSharedMemorySize,
                         SMEM_GF);
    gemm_out_f16<<<dim3(16, 32), 256, SMEM_GF>>>(bo, out);
}